// round 1
// baseline (speedup 1.0000x reference)
#include <cuda_runtime.h>
#include <math.h>

#define DIM   128
#define NTOK  98
#define HEADS 4
#define HD    32
#define BWIN  2048
#define NWIN  256

#define QKV_STRIDE 132
#define QKV_SEC    (NTOK * QKV_STRIDE)      // 12936 floats per q/k/v section
#define OFF_Q      0
#define OFF_K      QKV_SEC
#define OFF_V      (2 * QKV_SEC)
#define OFF_B2     (3 * QKV_SEC)            // xs, later out accumulator (98x132)
#define OFF_B3     (OFF_B2 + QKV_SEC)       // wtile (32x128) / S (56x100)
#define SS         100
#define SMEM_FLOATS (OFF_B3 + 5600)         // 57344 floats
#define SMEM_BYTES  (SMEM_FLOATS * 4)       // 229376 B  (< 232448 max opt-in)

// Precomputed per-head relative-position bias: g_bias[h][i][j]
__device__ float g_bias[HEADS * NTOK * NTOK];

__global__ void bias_setup_kernel(const float* __restrict__ bias_table,
                                  const int* __restrict__ rel_index) {
    int idx = blockIdx.x * blockDim.x + threadIdx.x;
    if (idx < NTOK * NTOK) {
        int ri = rel_index[idx];
#pragma unroll
        for (int h = 0; h < HEADS; h++)
            g_bias[h * (NTOK * NTOK) + idx] = bias_table[ri * HEADS + h];
    }
}

__global__ void __launch_bounds__(256, 1)
win_attn_kernel(const float* __restrict__ x, const float* __restrict__ mask,
                const float* __restrict__ qkv_w, const float* __restrict__ qkv_b,
                const float* __restrict__ proj_w, const float* __restrict__ proj_b,
                float* __restrict__ y) {
    extern __shared__ float sm[];
    const int b   = blockIdx.x;
    const int tid = threadIdx.x;

    // ---------------- Phase 0: load x window into smem (xs = buf2) ------------
    {
        const float4* xg = reinterpret_cast<const float4*>(x + (size_t)b * NTOK * DIM);
        for (int idx = tid; idx < NTOK * DIM / 4; idx += 256) {
            int r = idx >> 5, c4 = idx & 31;
            *reinterpret_cast<float4*>(&sm[OFF_B2 + r * QKV_STRIDE + c4 * 4]) = xg[idx];
        }
    }

    // ---------------- Phase 1: QKV GEMM (3 passes: q, k, v) ------------------
    {
        const int ty = tid >> 4, tx = tid & 15;   // 16 x 16 thread grid
        float* wt = sm + OFF_B3;                  // wtile_t[32][128] (k-major)
#pragma unroll 1
        for (int p = 0; p < 3; p++) {
            float acc[7][8];
#pragma unroll
            for (int i = 0; i < 7; i++)
#pragma unroll
                for (int j = 0; j < 8; j++) acc[i][j] = 0.f;

#pragma unroll 1
            for (int k0 = 0; k0 < DIM; k0 += 32) {
                __syncthreads();   // protect wt before overwrite
                // load weight chunk transposed: wt[kk][c] = w[p*128+c][k0+kk]
#pragma unroll
                for (int it = 0; it < 4; it++) {
                    int f = it * 256 + tid;        // 0..1023
                    int c = f >> 3;                // 0..127
                    int kq = (f & 7) << 2;         // 0,4,...,28
                    float4 w4 = *reinterpret_cast<const float4*>(
                        &qkv_w[(size_t)(p * DIM + c) * DIM + k0 + kq]);
                    wt[(kq + 0) * DIM + c] = w4.x;
                    wt[(kq + 1) * DIM + c] = w4.y;
                    wt[(kq + 2) * DIM + c] = w4.z;
                    wt[(kq + 3) * DIM + c] = w4.w;
                }
                __syncthreads();
#pragma unroll
                for (int kk4 = 0; kk4 < 8; kk4++) {
                    float4 a4[7];
#pragma unroll
                    for (int i = 0; i < 7; i++)
                        a4[i] = *reinterpret_cast<const float4*>(
                            &sm[OFF_B2 + (ty * 7 + i) * QKV_STRIDE + k0 + kk4 * 4]);
#pragma unroll
                    for (int u = 0; u < 4; u++) {
                        const float4 b0 = *reinterpret_cast<const float4*>(
                            &wt[(kk4 * 4 + u) * DIM + tx * 4]);
                        const float4 b1 = *reinterpret_cast<const float4*>(
                            &wt[(kk4 * 4 + u) * DIM + 64 + tx * 4]);
#pragma unroll
                        for (int i = 0; i < 7; i++) {
                            float av = (u == 0) ? a4[i].x : (u == 1) ? a4[i].y
                                       : (u == 2) ? a4[i].z : a4[i].w;
                            acc[i][0] += av * b0.x; acc[i][1] += av * b0.y;
                            acc[i][2] += av * b0.z; acc[i][3] += av * b0.w;
                            acc[i][4] += av * b1.x; acc[i][5] += av * b1.y;
                            acc[i][6] += av * b1.z; acc[i][7] += av * b1.w;
                        }
                    }
                }
            }
            // epilogue: + bias, scale q, store to qkv smem section
            const float4 bb0 = *reinterpret_cast<const float4*>(&qkv_b[p * DIM + tx * 4]);
            const float4 bb1 = *reinterpret_cast<const float4*>(&qkv_b[p * DIM + 64 + tx * 4]);
            const float qs = (p == 0) ? 0.17677669529663687f : 1.0f;   // 32^-0.5
#pragma unroll
            for (int i = 0; i < 7; i++) {
                int r = ty * 7 + i;
                if (r < NTOK) {
                    float4 v0, v1;
                    v0.x = (acc[i][0] + bb0.x) * qs;
                    v0.y = (acc[i][1] + bb0.y) * qs;
                    v0.z = (acc[i][2] + bb0.z) * qs;
                    v0.w = (acc[i][3] + bb0.w) * qs;
                    v1.x = (acc[i][4] + bb1.x) * qs;
                    v1.y = (acc[i][5] + bb1.y) * qs;
                    v1.z = (acc[i][6] + bb1.z) * qs;
                    v1.w = (acc[i][7] + bb1.w) * qs;
                    *reinterpret_cast<float4*>(&sm[p * QKV_SEC + r * QKV_STRIDE + tx * 4]) = v0;
                    *reinterpret_cast<float4*>(&sm[p * QKV_SEC + r * QKV_STRIDE + 64 + tx * 4]) = v1;
                }
            }
        }
        __syncthreads();
    }

    // ---------------- Phase 2/3: attention per head, per 49-row block --------
    {
        const int wq   = tid >> 5;   // warp 0..7
        const int lane = tid & 31;
        float* S    = sm + OFF_B3;   // [56][100]
        float* outs = sm + OFF_B2;   // reuse xs region as out accumulator
        const float* maskw = mask + (size_t)(b & (NWIN - 1)) * (NTOK * NTOK);

#pragma unroll 1
        for (int h = 0; h < HEADS; h++) {
#pragma unroll 1
            for (int rb = 0; rb < 2; rb++) {
                const int r0 = rb * 49;
                // ---- S = q @ k^T  (49 x 98, K=32) ----
                float acc[7][4];
#pragma unroll
                for (int i = 0; i < 7; i++)
#pragma unroll
                    for (int j = 0; j < 4; j++) acc[i][j] = 0.f;
#pragma unroll
                for (int d4 = 0; d4 < 8; d4++) {
                    float4 a4[7];
#pragma unroll
                    for (int i = 0; i < 7; i++)
                        a4[i] = *reinterpret_cast<const float4*>(
                            &sm[OFF_Q + (r0 + wq * 7 + i) * QKV_STRIDE + h * HD + d4 * 4]);
#pragma unroll
                    for (int j = 0; j < 4; j++) {
                        float4 b4 = *reinterpret_cast<const float4*>(
                            &sm[OFF_K + (lane + 32 * j) * QKV_STRIDE + h * HD + d4 * 4]);
#pragma unroll
                        for (int i = 0; i < 7; i++)
                            acc[i][j] += a4[i].x * b4.x + a4[i].y * b4.y +
                                         a4[i].z * b4.z + a4[i].w * b4.w;
                    }
                }
                // epilogue: + bias + mask, store S
#pragma unroll
                for (int i = 0; i < 7; i++) {
                    int lr = wq * 7 + i;
                    if (lr < 49) {
                        int gi = r0 + lr;
#pragma unroll
                        for (int j = 0; j < 4; j++) {
                            int gj = lane + 32 * j;
                            if (gj < NTOK) {
                                S[lr * SS + gj] = acc[i][j]
                                    + g_bias[h * (NTOK * NTOK) + gi * NTOK + gj]
                                    + maskw[gi * NTOK + gj];
                            }
                        }
                    }
                }
                __syncthreads();

                // ---- softmax over rows ----
                for (int r = wq; r < 49; r += 8) {
                    float* Sr = S + r * SS;
                    float v0 = Sr[lane], v1 = Sr[lane + 32], v2 = Sr[lane + 64];
                    float v3 = (lane < 2) ? Sr[lane + 96] : -3.0e38f;
                    float mx = fmaxf(fmaxf(v0, v1), fmaxf(v2, v3));
#pragma unroll
                    for (int o = 16; o > 0; o >>= 1)
                        mx = fmaxf(mx, __shfl_xor_sync(0xffffffffu, mx, o));
                    float e0 = __expf(v0 - mx), e1 = __expf(v1 - mx), e2 = __expf(v2 - mx);
                    float e3 = (lane < 2) ? __expf(v3 - mx) : 0.f;
                    float s = e0 + e1 + e2 + e3;
#pragma unroll
                    for (int o = 16; o > 0; o >>= 1)
                        s += __shfl_xor_sync(0xffffffffu, s, o);
                    float inv = 1.0f / s;
                    Sr[lane]      = e0 * inv;
                    Sr[lane + 32] = e1 * inv;
                    Sr[lane + 64] = e2 * inv;
                    if (lane < 2)      Sr[lane + 96] = e3 * inv;
                    else if (lane < 4) Sr[lane + 96] = 0.f;   // zero-pad cols 98,99
                }
                __syncthreads();

                // ---- O_h = P @ v_h  (49 x 32, K=98 padded to 100) ----
                {
                    float po[7] = {0.f, 0.f, 0.f, 0.f, 0.f, 0.f, 0.f};
#pragma unroll 5
                    for (int j4 = 0; j4 < 25; j4++) {
                        float bv0 = sm[OFF_V + (j4 * 4 + 0) * QKV_STRIDE + h * HD + lane];
                        float bv1 = sm[OFF_V + (j4 * 4 + 1) * QKV_STRIDE + h * HD + lane];
                        float bv2 = sm[OFF_V + (j4 * 4 + 2) * QKV_STRIDE + h * HD + lane];
                        float bv3 = sm[OFF_V + (j4 * 4 + 3) * QKV_STRIDE + h * HD + lane];
#pragma unroll
                        for (int i = 0; i < 7; i++) {
                            float4 a4 = *reinterpret_cast<const float4*>(
                                &S[(wq * 7 + i) * SS + j4 * 4]);
                            po[i] += a4.x * bv0 + a4.y * bv1 + a4.z * bv2 + a4.w * bv3;
                        }
                    }
#pragma unroll
                    for (int i = 0; i < 7; i++) {
                        int lr = wq * 7 + i;
                        if (lr < 49)
                            outs[(r0 + lr) * QKV_STRIDE + h * HD + lane] = po[i];
                    }
                }
                __syncthreads();
            }
        }
    }

    // ---------------- Phase 4: proj GEMM, write to gmem ----------------------
    {
        const int ty = tid >> 4, tx = tid & 15;
        float* wt = sm + OFF_B3;
        float acc[7][8];
#pragma unroll
        for (int i = 0; i < 7; i++)
#pragma unroll
            for (int j = 0; j < 8; j++) acc[i][j] = 0.f;

#pragma unroll 1
        for (int k0 = 0; k0 < DIM; k0 += 32) {
            __syncthreads();
#pragma unroll
            for (int it = 0; it < 4; it++) {
                int f = it * 256 + tid;
                int c = f >> 3;
                int kq = (f & 7) << 2;
                float4 w4 = *reinterpret_cast<const float4*>(
                    &proj_w[(size_t)c * DIM + k0 + kq]);
                wt[(kq + 0) * DIM + c] = w4.x;
                wt[(kq + 1) * DIM + c] = w4.y;
                wt[(kq + 2) * DIM + c] = w4.z;
                wt[(kq + 3) * DIM + c] = w4.w;
            }
            __syncthreads();
#pragma unroll
            for (int kk4 = 0; kk4 < 8; kk4++) {
                float4 a4[7];
#pragma unroll
                for (int i = 0; i < 7; i++)
                    a4[i] = *reinterpret_cast<const float4*>(
                        &sm[OFF_B2 + (ty * 7 + i) * QKV_STRIDE + k0 + kk4 * 4]);
#pragma unroll
                for (int u = 0; u < 4; u++) {
                    const float4 b0 = *reinterpret_cast<const float4*>(
                        &wt[(kk4 * 4 + u) * DIM + tx * 4]);
                    const float4 b1 = *reinterpret_cast<const float4*>(
                        &wt[(kk4 * 4 + u) * DIM + 64 + tx * 4]);
#pragma unroll
                    for (int i = 0; i < 7; i++) {
                        float av = (u == 0) ? a4[i].x : (u == 1) ? a4[i].y
                                   : (u == 2) ? a4[i].z : a4[i].w;
                        acc[i][0] += av * b0.x; acc[i][1] += av * b0.y;
                        acc[i][2] += av * b0.z; acc[i][3] += av * b0.w;
                        acc[i][4] += av * b1.x; acc[i][5] += av * b1.y;
                        acc[i][6] += av * b1.z; acc[i][7] += av * b1.w;
                    }
                }
            }
        }
        const float4 pb0 = *reinterpret_cast<const float4*>(&proj_b[tx * 4]);
        const float4 pb1 = *reinterpret_cast<const float4*>(&proj_b[64 + tx * 4]);
        float* yb = y + (size_t)b * NTOK * DIM;
#pragma unroll
        for (int i = 0; i < 7; i++) {
            int r = ty * 7 + i;
            if (r < NTOK) {
                float4 v0, v1;
                v0.x = acc[i][0] + pb0.x; v0.y = acc[i][1] + pb0.y;
                v0.z = acc[i][2] + pb0.z; v0.w = acc[i][3] + pb0.w;
                v1.x = acc[i][4] + pb1.x; v1.y = acc[i][5] + pb1.y;
                v1.z = acc[i][6] + pb1.z; v1.w = acc[i][7] + pb1.w;
                *reinterpret_cast<float4*>(&yb[r * DIM + tx * 4]) = v0;
                *reinterpret_cast<float4*>(&yb[r * DIM + 64 + tx * 4]) = v1;
            }
        }
    }
}

extern "C" void kernel_launch(void* const* d_in, const int* in_sizes, int n_in,
                              void* d_out, int out_size) {
    const float* x          = (const float*)d_in[0];
    const float* mask       = (const float*)d_in[1];
    const float* qkv_w      = (const float*)d_in[2];
    const float* qkv_b      = (const float*)d_in[3];
    const float* proj_w     = (const float*)d_in[4];
    const float* proj_b     = (const float*)d_in[5];
    const float* bias_table = (const float*)d_in[6];
    const int*   rel_index  = (const int*)d_in[7];
    float* y = (float*)d_out;

    (void)in_sizes; (void)n_in; (void)out_size;

    cudaFuncSetAttribute(win_attn_kernel,
                         cudaFuncAttributeMaxDynamicSharedMemorySize, SMEM_BYTES);

    bias_setup_kernel<<<(NTOK * NTOK + 255) / 256, 256>>>(bias_table, rel_index);
    win_attn_kernel<<<BWIN, 256, SMEM_BYTES>>>(x, mask, qkv_w, qkv_b,
                                               proj_w, proj_b, y);
}

// round 2
// speedup vs baseline: 1.0654x; 1.0654x over previous
#include <cuda_runtime.h>
#include <math.h>

#define DIM   128
#define NTOK  98
#define HEADS 4
#define HD    32
#define BWIN  2048
#define NWIN  256

#define QKV_STRIDE 132
#define QKV_SEC    (NTOK * QKV_STRIDE)      // 12936 floats per q/k/v section
#define OFF_Q      0
#define OFF_K      QKV_SEC
#define OFF_V      (2 * QKV_SEC)
#define OFF_B2     (3 * QKV_SEC)            // xs, later out accumulator (98x132)
#define OFF_B3     (OFF_B2 + QKV_SEC)       // wtile (32x128) / S (56x100)
#define SS         100
#define SMEM_FLOATS (OFF_B3 + 5600)         // 57344 floats
#define SMEM_BYTES  (SMEM_FLOATS * 4)       // 229376 B

typedef unsigned long long u64;

// ---------------- packed f32x2 helpers (Blackwell FFMA2 path) ----------------
__device__ __forceinline__ u64 pack2(float a, float b) {
    u64 r; asm("mov.b64 %0, {%1, %2};" : "=l"(r) : "f"(a), "f"(b)); return r;
}
__device__ __forceinline__ u64 bcast2(float a) {
    u64 r; asm("mov.b64 %0, {%1, %1};" : "=l"(r) : "f"(a)); return r;
}
__device__ __forceinline__ void fma2(u64& d, u64 a, u64 b) {
    asm("fma.rn.f32x2 %0, %1, %2, %3;" : "=l"(d) : "l"(a), "l"(b), "l"(d));
}
__device__ __forceinline__ u64 add2(u64 a, u64 b) {
    u64 r; asm("add.rn.f32x2 %0, %1, %2;" : "=l"(r) : "l"(a), "l"(b)); return r;
}
__device__ __forceinline__ u64 mul2(u64 a, u64 b) {
    u64 r; asm("mul.rn.f32x2 %0, %1, %2;" : "=l"(r) : "l"(a), "l"(b)); return r;
}
__device__ __forceinline__ float2 unpk2(u64 v) {
    float2 r; asm("mov.b64 {%0, %1}, %2;" : "=f"(r.x), "=f"(r.y) : "l"(v)); return r;
}

// Precomputed per-head relative-position bias: g_bias[h][i][j]
__device__ float g_bias[HEADS * NTOK * NTOK];

__global__ void bias_setup_kernel(const float* __restrict__ bias_table,
                                  const int* __restrict__ rel_index) {
    int idx = blockIdx.x * blockDim.x + threadIdx.x;
    if (idx < NTOK * NTOK) {
        int ri = rel_index[idx];
#pragma unroll
        for (int h = 0; h < HEADS; h++)
            g_bias[h * (NTOK * NTOK) + idx] = bias_table[ri * HEADS + h];
    }
}

__global__ void __launch_bounds__(256, 1)
win_attn_kernel(const float* __restrict__ x, const float* __restrict__ mask,
                const float* __restrict__ qkv_w, const float* __restrict__ qkv_b,
                const float* __restrict__ proj_w, const float* __restrict__ proj_b,
                float* __restrict__ y) {
    extern __shared__ float sm[];
    const int b   = blockIdx.x;
    const int tid = threadIdx.x;

    // ---------------- Phase 0: load x window into smem (xs = buf2) ------------
    {
        const float4* xg = reinterpret_cast<const float4*>(x + (size_t)b * NTOK * DIM);
        for (int idx = tid; idx < NTOK * DIM / 4; idx += 256) {
            int r = idx >> 5, c4 = idx & 31;
            *reinterpret_cast<float4*>(&sm[OFF_B2 + r * QKV_STRIDE + c4 * 4]) = xg[idx];
        }
    }

    // ---------------- Phase 1: QKV GEMM (3 passes: q, k, v) ------------------
    {
        const int ty = tid >> 4, tx = tid & 15;   // 16 x 16 thread grid
        float* wt = sm + OFF_B3;                  // wtile_t[32][128] (k-major)
#pragma unroll 1
        for (int p = 0; p < 3; p++) {
            u64 acc2[7][4];                       // [row][colpair]  (8 cols)
#pragma unroll
            for (int i = 0; i < 7; i++)
#pragma unroll
                for (int j = 0; j < 4; j++) acc2[i][j] = 0ull;

#pragma unroll 1
            for (int k0 = 0; k0 < DIM; k0 += 32) {
                __syncthreads();   // protect wt before overwrite
                // load weight chunk transposed: wt[kk][c] = w[p*128+c][k0+kk]
#pragma unroll
                for (int it = 0; it < 4; it++) {
                    int f = it * 256 + tid;        // 0..1023
                    int c = f >> 3;                // 0..127
                    int kq = (f & 7) << 2;         // 0,4,...,28
                    float4 w4 = *reinterpret_cast<const float4*>(
                        &qkv_w[(size_t)(p * DIM + c) * DIM + k0 + kq]);
                    wt[(kq + 0) * DIM + c] = w4.x;
                    wt[(kq + 1) * DIM + c] = w4.y;
                    wt[(kq + 2) * DIM + c] = w4.z;
                    wt[(kq + 3) * DIM + c] = w4.w;
                }
                __syncthreads();
#pragma unroll
                for (int kk4 = 0; kk4 < 8; kk4++) {
                    float4 a4[7];
#pragma unroll
                    for (int i = 0; i < 7; i++)
                        a4[i] = *reinterpret_cast<const float4*>(
                            &sm[OFF_B2 + (ty * 7 + i) * QKV_STRIDE + k0 + kk4 * 4]);
#pragma unroll
                    for (int u = 0; u < 4; u++) {
                        const ulonglong2 b0 = *reinterpret_cast<const ulonglong2*>(
                            &wt[(kk4 * 4 + u) * DIM + tx * 4]);
                        const ulonglong2 b1 = *reinterpret_cast<const ulonglong2*>(
                            &wt[(kk4 * 4 + u) * DIM + 64 + tx * 4]);
#pragma unroll
                        for (int i = 0; i < 7; i++) {
                            float av = (u == 0) ? a4[i].x : (u == 1) ? a4[i].y
                                       : (u == 2) ? a4[i].z : a4[i].w;
                            u64 av2 = bcast2(av);
                            fma2(acc2[i][0], av2, b0.x);
                            fma2(acc2[i][1], av2, b0.y);
                            fma2(acc2[i][2], av2, b1.x);
                            fma2(acc2[i][3], av2, b1.y);
                        }
                    }
                }
            }
            // epilogue: + bias, scale q, store to qkv smem section
            const ulonglong2 bb0 = *reinterpret_cast<const ulonglong2*>(&qkv_b[p * DIM + tx * 4]);
            const ulonglong2 bb1 = *reinterpret_cast<const ulonglong2*>(&qkv_b[p * DIM + 64 + tx * 4]);
            const u64 qs2 = bcast2((p == 0) ? 0.17677669529663687f : 1.0f);   // 32^-0.5
#pragma unroll
            for (int i = 0; i < 7; i++) {
                int r = ty * 7 + i;
                if (r < NTOK) {
                    ulonglong2 v0, v1;
                    v0.x = mul2(add2(acc2[i][0], bb0.x), qs2);
                    v0.y = mul2(add2(acc2[i][1], bb0.y), qs2);
                    v1.x = mul2(add2(acc2[i][2], bb1.x), qs2);
                    v1.y = mul2(add2(acc2[i][3], bb1.y), qs2);
                    *reinterpret_cast<ulonglong2*>(&sm[p * QKV_SEC + r * QKV_STRIDE + tx * 4]) = v0;
                    *reinterpret_cast<ulonglong2*>(&sm[p * QKV_SEC + r * QKV_STRIDE + 64 + tx * 4]) = v1;
                }
            }
        }
        __syncthreads();
    }

    // ---------------- Phase 2/3: attention per head, per 49-row block --------
    {
        const int wq   = tid >> 5;   // warp 0..7
        const int lane = tid & 31;
        float* S    = sm + OFF_B3;   // [56][100]
        float* outs = sm + OFF_B2;   // reuse xs region as out accumulator
        const float* maskw = mask + (size_t)(b & (NWIN - 1)) * (NTOK * NTOK);

#pragma unroll 1
        for (int h = 0; h < HEADS; h++) {
#pragma unroll 1
            for (int rb = 0; rb < 2; rb++) {
                const int r0 = rb * 49;
                // ---- S = q @ k^T  (49 x 98, K=32), f32x2 packed over d ----
                u64 acc2[7][4];
#pragma unroll
                for (int i = 0; i < 7; i++)
#pragma unroll
                    for (int j = 0; j < 4; j++) acc2[i][j] = 0ull;
#pragma unroll
                for (int d4 = 0; d4 < 8; d4++) {
                    ulonglong2 a2[7];
#pragma unroll
                    for (int i = 0; i < 7; i++)
                        a2[i] = *reinterpret_cast<const ulonglong2*>(
                            &sm[OFF_Q + (r0 + wq * 7 + i) * QKV_STRIDE + h * HD + d4 * 4]);
#pragma unroll
                    for (int j = 0; j < 4; j++) {
                        ulonglong2 b2 = *reinterpret_cast<const ulonglong2*>(
                            &sm[OFF_K + (lane + 32 * j) * QKV_STRIDE + h * HD + d4 * 4]);
#pragma unroll
                        for (int i = 0; i < 7; i++) {
                            fma2(acc2[i][j], a2[i].x, b2.x);
                            fma2(acc2[i][j], a2[i].y, b2.y);
                        }
                    }
                }
                // epilogue: horizontal add, + bias + mask, store S
#pragma unroll
                for (int i = 0; i < 7; i++) {
                    int lr = wq * 7 + i;
                    if (lr < 49) {
                        int gi = r0 + lr;
#pragma unroll
                        for (int j = 0; j < 3; j++) {
                            int gj = lane + 32 * j;
                            float2 pp = unpk2(acc2[i][j]);
                            S[lr * SS + gj] = pp.x + pp.y
                                + g_bias[h * (NTOK * NTOK) + gi * NTOK + gj]
                                + maskw[gi * NTOK + gj];
                        }
                        int gj = lane + 96;
                        if (gj < NTOK) {
                            float2 pp = unpk2(acc2[i][3]);
                            S[lr * SS + gj] = pp.x + pp.y
                                + g_bias[h * (NTOK * NTOK) + gi * NTOK + gj]
                                + maskw[gi * NTOK + gj];
                        }
                    }
                }
                __syncthreads();

                // ---- softmax over rows ----
                for (int r = wq; r < 49; r += 8) {
                    float* Sr = S + r * SS;
                    float v0 = Sr[lane], v1 = Sr[lane + 32], v2 = Sr[lane + 64];
                    float v3 = (lane < 2) ? Sr[lane + 96] : -3.0e38f;
                    float mx = fmaxf(fmaxf(v0, v1), fmaxf(v2, v3));
#pragma unroll
                    for (int o = 16; o > 0; o >>= 1)
                        mx = fmaxf(mx, __shfl_xor_sync(0xffffffffu, mx, o));
                    float e0 = __expf(v0 - mx), e1 = __expf(v1 - mx), e2 = __expf(v2 - mx);
                    float e3 = (lane < 2) ? __expf(v3 - mx) : 0.f;
                    float s = e0 + e1 + e2 + e3;
#pragma unroll
                    for (int o = 16; o > 0; o >>= 1)
                        s += __shfl_xor_sync(0xffffffffu, s, o);
                    float inv = 1.0f / s;
                    Sr[lane]      = e0 * inv;
                    Sr[lane + 32] = e1 * inv;
                    Sr[lane + 64] = e2 * inv;
                    if (lane < 2)      Sr[lane + 96] = e3 * inv;
                    else if (lane < 4) Sr[lane + 96] = 0.f;   // zero-pad cols 98,99
                }
                __syncthreads();

                // ---- O_h = P @ v_h  (49 x 32, K=98 padded to 100), f32x2 over j ----
                {
                    u64 po2[7];
#pragma unroll
                    for (int i = 0; i < 7; i++) po2[i] = 0ull;
#pragma unroll 5
                    for (int j4 = 0; j4 < 25; j4++) {
                        float bv0 = sm[OFF_V + (j4 * 4 + 0) * QKV_STRIDE + h * HD + lane];
                        float bv1 = sm[OFF_V + (j4 * 4 + 1) * QKV_STRIDE + h * HD + lane];
                        float bv2 = sm[OFF_V + (j4 * 4 + 2) * QKV_STRIDE + h * HD + lane];
                        float bv3 = sm[OFF_V + (j4 * 4 + 3) * QKV_STRIDE + h * HD + lane];
                        u64 v01 = pack2(bv0, bv1);
                        u64 v23 = pack2(bv2, bv3);
#pragma unroll
                        for (int i = 0; i < 7; i++) {
                            ulonglong2 a2 = *reinterpret_cast<const ulonglong2*>(
                                &S[(wq * 7 + i) * SS + j4 * 4]);
                            fma2(po2[i], a2.x, v01);
                            fma2(po2[i], a2.y, v23);
                        }
                    }
#pragma unroll
                    for (int i = 0; i < 7; i++) {
                        int lr = wq * 7 + i;
                        if (lr < 49) {
                            float2 pp = unpk2(po2[i]);
                            outs[(r0 + lr) * QKV_STRIDE + h * HD + lane] = pp.x + pp.y;
                        }
                    }
                }
                __syncthreads();
            }
        }
    }

    // ---------------- Phase 4: proj GEMM, write to gmem ----------------------
    {
        const int ty = tid >> 4, tx = tid & 15;
        float* wt = sm + OFF_B3;
        u64 acc2[7][4];
#pragma unroll
        for (int i = 0; i < 7; i++)
#pragma unroll
            for (int j = 0; j < 4; j++) acc2[i][j] = 0ull;

#pragma unroll 1
        for (int k0 = 0; k0 < DIM; k0 += 32) {
            __syncthreads();
#pragma unroll
            for (int it = 0; it < 4; it++) {
                int f = it * 256 + tid;
                int c = f >> 3;
                int kq = (f & 7) << 2;
                float4 w4 = *reinterpret_cast<const float4*>(
                    &proj_w[(size_t)c * DIM + k0 + kq]);
                wt[(kq + 0) * DIM + c] = w4.x;
                wt[(kq + 1) * DIM + c] = w4.y;
                wt[(kq + 2) * DIM + c] = w4.z;
                wt[(kq + 3) * DIM + c] = w4.w;
            }
            __syncthreads();
#pragma unroll
            for (int kk4 = 0; kk4 < 8; kk4++) {
                float4 a4[7];
#pragma unroll
                for (int i = 0; i < 7; i++)
                    a4[i] = *reinterpret_cast<const float4*>(
                        &sm[OFF_B2 + (ty * 7 + i) * QKV_STRIDE + k0 + kk4 * 4]);
#pragma unroll
                for (int u = 0; u < 4; u++) {
                    const ulonglong2 b0 = *reinterpret_cast<const ulonglong2*>(
                        &wt[(kk4 * 4 + u) * DIM + tx * 4]);
                    const ulonglong2 b1 = *reinterpret_cast<const ulonglong2*>(
                        &wt[(kk4 * 4 + u) * DIM + 64 + tx * 4]);
#pragma unroll
                    for (int i = 0; i < 7; i++) {
                        float av = (u == 0) ? a4[i].x : (u == 1) ? a4[i].y
                                   : (u == 2) ? a4[i].z : a4[i].w;
                        u64 av2 = bcast2(av);
                        fma2(acc2[i][0], av2, b0.x);
                        fma2(acc2[i][1], av2, b0.y);
                        fma2(acc2[i][2], av2, b1.x);
                        fma2(acc2[i][3], av2, b1.y);
                    }
                }
            }
        }
        const ulonglong2 pb0 = *reinterpret_cast<const ulonglong2*>(&proj_b[tx * 4]);
        const ulonglong2 pb1 = *reinterpret_cast<const ulonglong2*>(&proj_b[64 + tx * 4]);
        float* yb = y + (size_t)b * NTOK * DIM;
#pragma unroll
        for (int i = 0; i < 7; i++) {
            int r = ty * 7 + i;
            if (r < NTOK) {
                ulonglong2 v0, v1;
                v0.x = add2(acc2[i][0], pb0.x);
                v0.y = add2(acc2[i][1], pb0.y);
                v1.x = add2(acc2[i][2], pb1.x);
                v1.y = add2(acc2[i][3], pb1.y);
                *reinterpret_cast<ulonglong2*>(&yb[r * DIM + tx * 4]) = v0;
                *reinterpret_cast<ulonglong2*>(&yb[r * DIM + 64 + tx * 4]) = v1;
            }
        }
    }
}

extern "C" void kernel_launch(void* const* d_in, const int* in_sizes, int n_in,
                              void* d_out, int out_size) {
    const float* x          = (const float*)d_in[0];
    const float* mask       = (const float*)d_in[1];
    const float* qkv_w      = (const float*)d_in[2];
    const float* qkv_b      = (const float*)d_in[3];
    const float* proj_w     = (const float*)d_in[4];
    const float* proj_b     = (const float*)d_in[5];
    const float* bias_table = (const float*)d_in[6];
    const int*   rel_index  = (const int*)d_in[7];
    float* y = (float*)d_out;

    (void)in_sizes; (void)n_in; (void)out_size;

    cudaFuncSetAttribute(win_attn_kernel,
                         cudaFuncAttributeMaxDynamicSharedMemorySize, SMEM_BYTES);

    bias_setup_kernel<<<(NTOK * NTOK + 255) / 256, 256>>>(bias_table, rel_index);
    win_attn_kernel<<<BWIN, 256, SMEM_BYTES>>>(x, mask, qkv_w, qkv_b,
                                               proj_w, proj_b, y);
}

// round 3
// speedup vs baseline: 1.1127x; 1.0444x over previous
#include <cuda_runtime.h>
#include <math.h>

#define DIM   128
#define NTOK  98
#define HEADS 4
#define HD    32
#define BWIN  2048
#define NWIN  256

#define QKV_STRIDE 132
#define QKV_SEC    (NTOK * QKV_STRIDE)      // 12936 floats per q/k/v section
#define OFF_Q      0
#define OFF_K      QKV_SEC
#define OFF_V      (2 * QKV_SEC)
#define OFF_B2     (3 * QKV_SEC)            // xs, later out accumulator (98x132)
#define OFF_B3     (OFF_B2 + QKV_SEC)       // wtile (32x128) / S (56x100)
#define SS         100
#define SMEM_FLOATS (OFF_B3 + 5600)         // 57344 floats
#define SMEM_BYTES  (SMEM_FLOATS * 4)       // 229376 B

typedef unsigned long long u64;

// ---------------- packed f32x2 helpers ----------------
__device__ __forceinline__ u64 pack2(float a, float b) {
    u64 r; asm("mov.b64 %0, {%1, %2};" : "=l"(r) : "f"(a), "f"(b)); return r;
}
__device__ __forceinline__ u64 bcast2(float a) {
    u64 r; asm("mov.b64 %0, {%1, %1};" : "=l"(r) : "f"(a)); return r;
}
__device__ __forceinline__ void fma2(u64& d, u64 a, u64 b) {
    asm("fma.rn.f32x2 %0, %1, %2, %3;" : "=l"(d) : "l"(a), "l"(b), "l"(d));
}
__device__ __forceinline__ u64 add2(u64 a, u64 b) {
    u64 r; asm("add.rn.f32x2 %0, %1, %2;" : "=l"(r) : "l"(a), "l"(b)); return r;
}
__device__ __forceinline__ u64 mul2(u64 a, u64 b) {
    u64 r; asm("mul.rn.f32x2 %0, %1, %2;" : "=l"(r) : "l"(a), "l"(b)); return r;
}
__device__ __forceinline__ float2 unpk2(u64 v) {
    float2 r; asm("mov.b64 {%0, %1}, %2;" : "=f"(r.x), "=f"(r.y) : "l"(v)); return r;
}

// Precomputed per-head bias + transposed weights (k-major)
__device__ float g_bias[HEADS * NTOK * NTOK];
__device__ float g_wqkvT[3 * DIM * DIM];   // [p][k][c] = qkv_w[p*128+c][k]
__device__ float g_wprojT[DIM * DIM];      // [k][c]    = proj_w[c][k]

__global__ void bias_setup_kernel(const float* __restrict__ bias_table,
                                  const int* __restrict__ rel_index) {
    int idx = blockIdx.x * blockDim.x + threadIdx.x;
    if (idx < NTOK * NTOK) {
        int ri = rel_index[idx];
#pragma unroll
        for (int h = 0; h < HEADS; h++)
            g_bias[h * (NTOK * NTOK) + idx] = bias_table[ri * HEADS + h];
    }
}

__global__ void wtranspose_kernel(const float* __restrict__ qkv_w,
                                  const float* __restrict__ proj_w) {
    int idx = blockIdx.x * blockDim.x + threadIdx.x;
    if (idx < 3 * DIM * DIM) {
        int p = idx >> 14;               // /16384
        int k = (idx >> 7) & 127;
        int c = idx & 127;
        g_wqkvT[idx] = qkv_w[(size_t)(p * DIM + c) * DIM + k];
    } else if (idx < 4 * DIM * DIM) {
        int i2 = idx - 3 * DIM * DIM;
        int k = i2 >> 7, c = i2 & 127;
        g_wprojT[i2] = proj_w[(size_t)c * DIM + k];
    }
}

// dense GEMM phase: out[r][c] (98x128) = A(98x128, smem strided 132) @ WT(k-major)
// warp owns rows (broadcast A loads), lane owns 4 cols.
__device__ __forceinline__ void dense_gemm(
    const float* __restrict__ wT,      // device global, k-major [128][128]
    float* sm, int srcOff,             // A rows at sm[srcOff + r*132 + k]
    int warp, int lane, int tid,
    u64 acc[7][2])
{
    float* wt = sm + OFF_B3;           // smem tile 32x128
#pragma unroll
    for (int i = 0; i < 7; i++) { acc[i][0] = 0ull; acc[i][1] = 0ull; }

#pragma unroll 1
    for (int c0 = 0; c0 < 4; c0++) {
        const int k0 = c0 * 32;
        __syncthreads();
        // fill wt[32][128] -- coalesced LDG.128, conflict-free STS.128
#pragma unroll
        for (int t = 0; t < 2; t++) {
            int f = t * 512 + tid;         // float4 index 0..1023: k=f>>5, c4=f&31
            float4 w4 = reinterpret_cast<const float4*>(wT)[(k0 + (f >> 5)) * 32 + (f & 31)];
            *reinterpret_cast<float4*>(&wt[(f >> 5) * DIM + (f & 31) * 4]) = w4;
        }
        __syncthreads();
#pragma unroll
        for (int kk4 = 0; kk4 < 8; kk4++) {
            float4 a4[7];
#pragma unroll
            for (int i = 0; i < 6; i++)
                a4[i] = *reinterpret_cast<const float4*>(
                    &sm[srcOff + (warp + 16 * i) * QKV_STRIDE + k0 + kk4 * 4]);
            if (warp < 2)
                a4[6] = *reinterpret_cast<const float4*>(
                    &sm[srcOff + (warp + 96) * QKV_STRIDE + k0 + kk4 * 4]);
#pragma unroll
            for (int u = 0; u < 4; u++) {
                const ulonglong2 b2 = *reinterpret_cast<const ulonglong2*>(
                    &wt[(kk4 * 4 + u) * DIM + lane * 4]);
#pragma unroll
                for (int i = 0; i < 6; i++) {
                    float av = (u == 0) ? a4[i].x : (u == 1) ? a4[i].y
                               : (u == 2) ? a4[i].z : a4[i].w;
                    u64 av2 = bcast2(av);
                    fma2(acc[i][0], av2, b2.x);
                    fma2(acc[i][1], av2, b2.y);
                }
                if (warp < 2) {
                    float av = (u == 0) ? a4[6].x : (u == 1) ? a4[6].y
                               : (u == 2) ? a4[6].z : a4[6].w;
                    u64 av2 = bcast2(av);
                    fma2(acc[6][0], av2, b2.x);
                    fma2(acc[6][1], av2, b2.y);
                }
            }
        }
    }
}

__global__ void __launch_bounds__(512, 1)
win_attn_kernel(const float* __restrict__ x, const float* __restrict__ mask,
                const float* __restrict__ qkv_b, const float* __restrict__ proj_b,
                float* __restrict__ y) {
    extern __shared__ float sm[];
    const int b    = blockIdx.x;
    const int tid  = threadIdx.x;
    const int warp = tid >> 5;    // 0..15
    const int lane = tid & 31;

    // ---------------- Phase 0: load x window into smem (OFF_B2) --------------
    {
        const float4* xg = reinterpret_cast<const float4*>(x + (size_t)b * NTOK * DIM);
        for (int idx = tid; idx < NTOK * DIM / 4; idx += 512) {
            int r = idx >> 5, c4 = idx & 31;
            *reinterpret_cast<float4*>(&sm[OFF_B2 + r * QKV_STRIDE + c4 * 4]) = xg[idx];
        }
    }

    // ---------------- Phase 1: QKV GEMM (3 passes) ---------------------------
#pragma unroll 1
    for (int p = 0; p < 3; p++) {
        u64 acc[7][2];
        dense_gemm(g_wqkvT + p * DIM * DIM, sm, OFF_B2, warp, lane, tid, acc);
        const ulonglong2 bb = *reinterpret_cast<const ulonglong2*>(&qkv_b[p * DIM + lane * 4]);
        const u64 qs2 = bcast2((p == 0) ? 0.17677669529663687f : 1.0f);
#pragma unroll
        for (int i = 0; i < 7; i++) {
            if (i < 6 || warp < 2) {
                int r = warp + 16 * i;
                ulonglong2 v;
                v.x = mul2(add2(acc[i][0], bb.x), qs2);
                v.y = mul2(add2(acc[i][1], bb.y), qs2);
                *reinterpret_cast<ulonglong2*>(&sm[p * QKV_SEC + r * QKV_STRIDE + lane * 4]) = v;
            }
        }
    }
    __syncthreads();

    // ---------------- Phase 2/3: attention per (head, row-block) -------------
    {
        const int w7 = warp & 7;
        const int jh = warp >> 3;         // 0: cols 0..63, 1: cols 64..97(127)
        float* S    = sm + OFF_B3;        // [56][100] (rows 0..48 used)
        float* outs = sm + OFF_B2;
        const float* maskw = mask + (size_t)(b & (NWIN - 1)) * (NTOK * NTOK);

#pragma unroll 1
        for (int h = 0; h < HEADS; h++) {
#pragma unroll 1
            for (int rb = 0; rb < 2; rb++) {
                const int r0 = rb * 49;
                // ---- S = q @ k^T : rows w7+8i (i<6, +i=6 for w7==0), col pair jh
                u64 acc[7][2];
#pragma unroll
                for (int i = 0; i < 7; i++) { acc[i][0] = 0ull; acc[i][1] = 0ull; }
#pragma unroll
                for (int d4 = 0; d4 < 8; d4++) {
                    ulonglong2 a2[7];
#pragma unroll
                    for (int i = 0; i < 6; i++)
                        a2[i] = *reinterpret_cast<const ulonglong2*>(
                            &sm[OFF_Q + (r0 + w7 + 8 * i) * QKV_STRIDE + h * HD + d4 * 4]);
                    if (w7 == 0)
                        a2[6] = *reinterpret_cast<const ulonglong2*>(
                            &sm[OFF_Q + (r0 + 48) * QKV_STRIDE + h * HD + d4 * 4]);
#pragma unroll
                    for (int jj = 0; jj < 2; jj++) {
                        int krow = lane + 32 * (2 * jh + jj);   // may exceed 97 (garbage ok)
                        ulonglong2 b2 = *reinterpret_cast<const ulonglong2*>(
                            &sm[OFF_K + krow * QKV_STRIDE + h * HD + d4 * 4]);
#pragma unroll
                        for (int i = 0; i < 6; i++) {
                            fma2(acc[i][jj], a2[i].x, b2.x);
                            fma2(acc[i][jj], a2[i].y, b2.y);
                        }
                        if (w7 == 0) {
                            fma2(acc[6][jj], a2[6].x, b2.x);
                            fma2(acc[6][jj], a2[6].y, b2.y);
                        }
                    }
                }
                // epilogue: horizontal add + bias + mask
#pragma unroll
                for (int i = 0; i < 7; i++) {
                    if (i < 6 || w7 == 0) {
                        int lr = w7 + 8 * i;
                        int gi = r0 + lr;
#pragma unroll
                        for (int jj = 0; jj < 2; jj++) {
                            int gj = lane + 32 * (2 * jh + jj);
                            if (gj < NTOK) {
                                float2 pp = unpk2(acc[i][jj]);
                                S[lr * SS + gj] = pp.x + pp.y
                                    + g_bias[h * (NTOK * NTOK) + gi * NTOK + gj]
                                    + maskw[gi * NTOK + gj];
                            }
                        }
                    }
                }
                __syncthreads();

                // ---- softmax over rows (49 rows over 16 warps) ----
                for (int r = warp; r < 49; r += 16) {
                    float* Sr = S + r * SS;
                    float v0 = Sr[lane], v1 = Sr[lane + 32], v2 = Sr[lane + 64];
                    float v3 = (lane < 2) ? Sr[lane + 96] : -3.0e38f;
                    float mx = fmaxf(fmaxf(v0, v1), fmaxf(v2, v3));
#pragma unroll
                    for (int o = 16; o > 0; o >>= 1)
                        mx = fmaxf(mx, __shfl_xor_sync(0xffffffffu, mx, o));
                    float e0 = __expf(v0 - mx), e1 = __expf(v1 - mx), e2 = __expf(v2 - mx);
                    float e3 = (lane < 2) ? __expf(v3 - mx) : 0.f;
                    float s = e0 + e1 + e2 + e3;
#pragma unroll
                    for (int o = 16; o > 0; o >>= 1)
                        s += __shfl_xor_sync(0xffffffffu, s, o);
                    float inv = 1.0f / s;
                    Sr[lane]      = e0 * inv;
                    Sr[lane + 32] = e1 * inv;
                    Sr[lane + 64] = e2 * inv;
                    if (lane < 2)      Sr[lane + 96] = e3 * inv;
                    else if (lane < 4) Sr[lane + 96] = 0.f;   // zero-pad cols 98,99
                }
                __syncthreads();

                // ---- O_h = P @ v_h : rows warp+16i (i<3, +i=3 for warp==0) ----
                {
                    u64 po2[4];
#pragma unroll
                    for (int i = 0; i < 4; i++) po2[i] = 0ull;
#pragma unroll 5
                    for (int j4 = 0; j4 < 25; j4++) {
                        float bv0 = sm[OFF_V + (j4 * 4 + 0) * QKV_STRIDE + h * HD + lane];
                        float bv1 = sm[OFF_V + (j4 * 4 + 1) * QKV_STRIDE + h * HD + lane];
                        float bv2 = sm[OFF_V + (j4 * 4 + 2) * QKV_STRIDE + h * HD + lane];
                        float bv3 = sm[OFF_V + (j4 * 4 + 3) * QKV_STRIDE + h * HD + lane];
                        u64 v01 = pack2(bv0, bv1);
                        u64 v23 = pack2(bv2, bv3);
#pragma unroll
                        for (int i = 0; i < 3; i++) {
                            ulonglong2 a2 = *reinterpret_cast<const ulonglong2*>(
                                &S[(warp + 16 * i) * SS + j4 * 4]);
                            fma2(po2[i], a2.x, v01);
                            fma2(po2[i], a2.y, v23);
                        }
                        if (warp == 0) {
                            ulonglong2 a2 = *reinterpret_cast<const ulonglong2*>(
                                &S[48 * SS + j4 * 4]);
                            fma2(po2[3], a2.x, v01);
                            fma2(po2[3], a2.y, v23);
                        }
                    }
#pragma unroll
                    for (int i = 0; i < 4; i++) {
                        if (i < 3 || warp == 0) {
                            int lr = warp + 16 * i;
                            float2 pp = unpk2(po2[i]);
                            outs[(r0 + lr) * QKV_STRIDE + h * HD + lane] = pp.x + pp.y;
                        }
                    }
                }
                __syncthreads();
            }
        }
    }

    // ---------------- Phase 4: proj GEMM, write to gmem ----------------------
    {
        u64 acc[7][2];
        dense_gemm(g_wprojT, sm, OFF_B2, warp, lane, tid, acc);
        const ulonglong2 pb = *reinterpret_cast<const ulonglong2*>(&proj_b[lane * 4]);
        float* yb = y + (size_t)b * NTOK * DIM;
#pragma unroll
        for (int i = 0; i < 7; i++) {
            if (i < 6 || warp < 2) {
                int r = warp + 16 * i;
                ulonglong2 v;
                v.x = add2(acc[i][0], pb.x);
                v.y = add2(acc[i][1], pb.y);
                *reinterpret_cast<ulonglong2*>(&yb[r * DIM + lane * 4]) = v;
            }
        }
    }
}

extern "C" void kernel_launch(void* const* d_in, const int* in_sizes, int n_in,
                              void* d_out, int out_size) {
    const float* x          = (const float*)d_in[0];
    const float* mask       = (const float*)d_in[1];
    const float* qkv_w      = (const float*)d_in[2];
    const float* qkv_b      = (const float*)d_in[3];
    const float* proj_w     = (const float*)d_in[4];
    const float* proj_b     = (const float*)d_in[5];
    const float* bias_table = (const float*)d_in[6];
    const int*   rel_index  = (const int*)d_in[7];
    float* y = (float*)d_out;

    (void)in_sizes; (void)n_in; (void)out_size;

    cudaFuncSetAttribute(win_attn_kernel,
                         cudaFuncAttributeMaxDynamicSharedMemorySize, SMEM_BYTES);

    bias_setup_kernel<<<(NTOK * NTOK + 255) / 256, 256>>>(bias_table, rel_index);
    wtranspose_kernel<<<(4 * DIM * DIM + 255) / 256, 256>>>(qkv_w, proj_w);
    win_attn_kernel<<<BWIN, 512, SMEM_BYTES>>>(x, mask, qkv_b, proj_b, y);
}

// round 7
// speedup vs baseline: 1.3583x; 1.2208x over previous
#include <cuda_runtime.h>
#include <cuda_bf16.h>
#include <cstdint>
#include <math.h>

#define DIM   128
#define NTOK  98
#define HEADS 4
#define BWIN  2048
#define NWIN  256
#define MTOT  (BWIN * NTOK)          // 200704 = 1568 * 128
#define MTILES 1568
#define QSCALE 0.17677669529663687f  // 32^-0.5

typedef unsigned long long u64;

// ---------------- f32x2 helpers ----------------
__device__ __forceinline__ u64 pack2(float a, float b) {
    u64 r; asm("mov.b64 %0, {%1, %2};" : "=l"(r) : "f"(a), "f"(b)); return r;
}
__device__ __forceinline__ void fma2(u64& d, u64 a, u64 b) {
    asm("fma.rn.f32x2 %0, %1, %2, %3;" : "=l"(d) : "l"(a), "l"(b), "l"(d));
}
__device__ __forceinline__ float2 unpk2(u64 v) {
    float2 r; asm("mov.b64 {%0, %1}, %2;" : "=f"(r.x), "=f"(r.y) : "l"(v)); return r;
}

// ---------------- HMMA m16n8k16 bf16 ----------------
__device__ __forceinline__ void mma16816(float* c, const uint32_t* a, const uint32_t* b) {
    asm volatile(
        "mma.sync.aligned.m16n8k16.row.col.f32.bf16.bf16.f32 "
        "{%0,%1,%2,%3}, {%4,%5,%6,%7}, {%8,%9}, {%0,%1,%2,%3};"
        : "+f"(c[0]), "+f"(c[1]), "+f"(c[2]), "+f"(c[3])
        : "r"(a[0]), "r"(a[1]), "r"(a[2]), "r"(a[3]), "r"(b[0]), "r"(b[1]));
}

// ---------------- device scratch ----------------
__device__ float g_qkv[(size_t)MTOT * 384];        // q(scaled+biased)|k|v per token
__device__ float g_o[(size_t)MTOT * DIM];          // attention output
__device__ float g_bias[HEADS * NTOK * NTOK];
__device__ __nv_bfloat16 g_wimg[4][2][DIM * DIM];  // W[n][k] bf16 hi/lo images

// ---------------- setup kernels ----------------
__global__ void bias_setup_kernel(const float* __restrict__ bias_table,
                                  const int* __restrict__ rel_index) {
    int idx = blockIdx.x * blockDim.x + threadIdx.x;
    if (idx < NTOK * NTOK) {
        int ri = rel_index[idx];
#pragma unroll
        for (int h = 0; h < HEADS; h++)
            g_bias[h * (NTOK * NTOK) + idx] = bias_table[ri * HEADS + h];
    }
}

__global__ void wimg_setup_kernel(const float* __restrict__ qkv_w,
                                  const float* __restrict__ proj_w) {
    int idx = blockIdx.x * blockDim.x + threadIdx.x;   // 65536 total
    int t = idx >> 14;
    int n = (idx >> 7) & 127;
    int k = idx & 127;
    float w = (t < 3) ? qkv_w[(size_t)(t * DIM + n) * DIM + k]
                      : proj_w[(size_t)n * DIM + k];
    __nv_bfloat16 hi = __float2bfloat16(w);
    __nv_bfloat16 lo = __float2bfloat16(w - __bfloat162float(hi));
    g_wimg[t][0][n * DIM + k] = hi;
    g_wimg[t][1][n * DIM + k] = lo;
}

// ---------------- GEMM: 128x128 tile, K=128, bf16-split HMMA -----------------
// smem stride: 136 bf16 = 272 B = 68 words (68 % 32 == 4 -> conflict-free frags)
#define STB  136
#define STW  68
#define TILE_B (128 * STB * 2)         // 34816 bytes per array
#define GA_HI  0
#define GA_LO  TILE_B
#define GB_HI  (2 * TILE_B)
#define GB_LO  (3 * TILE_B)
#define GS_TOTAL (4 * TILE_B)          // 139264 B

__global__ void __launch_bounds__(256, 1)
gemm128_kernel(const float* __restrict__ Ax, const float* __restrict__ bias,
               float* __restrict__ yout, int ostride, int wbase,
               int a_scratch, int out_scratch) {
    extern __shared__ char smg[];
    const int tid = threadIdx.x;
    const int by = blockIdx.y;
    const float* __restrict__ Asrc = a_scratch ? g_o : Ax;
    float* __restrict__ out = out_scratch ? g_qkv : yout;
    const size_t mrow0 = (size_t)blockIdx.x * 128;

    // ---- load B tiles (pre-split bf16 images) ----
    {
        const __nv_bfloat16* bh = g_wimg[wbase + by][0];
        const __nv_bfloat16* bl = g_wimg[wbase + by][1];
        for (int i = tid; i < 2048; i += 256) {
            int row = i >> 4, col = (i & 15) * 8;
            uint4 vh = *reinterpret_cast<const uint4*>(bh + row * DIM + col);
            uint4 vl = *reinterpret_cast<const uint4*>(bl + row * DIM + col);
            char* dh = smg + GB_HI + row * (STB * 2) + col * 2;
            char* dl = smg + GB_LO + row * (STB * 2) + col * 2;
            *reinterpret_cast<uint2*>(dh)     = make_uint2(vh.x, vh.y);
            *reinterpret_cast<uint2*>(dh + 8) = make_uint2(vh.z, vh.w);
            *reinterpret_cast<uint2*>(dl)     = make_uint2(vl.x, vl.y);
            *reinterpret_cast<uint2*>(dl + 8) = make_uint2(vl.z, vl.w);
        }
    }
    // ---- load + split A tile ----
    for (int i = tid; i < 2048; i += 256) {
        int row = i >> 4, col = (i & 15) * 8;
        const float* ap = Asrc + (mrow0 + row) * DIM + col;
        float4 f0 = *reinterpret_cast<const float4*>(ap);
        float4 f1 = *reinterpret_cast<const float4*>(ap + 4);
        float fv[8] = {f0.x, f0.y, f0.z, f0.w, f1.x, f1.y, f1.z, f1.w};
        __align__(16) __nv_bfloat16 hv[8], lv[8];
#pragma unroll
        for (int e = 0; e < 8; e++) {
            hv[e] = __float2bfloat16(fv[e]);
            lv[e] = __float2bfloat16(fv[e] - __bfloat162float(hv[e]));
        }
        char* dh = smg + GA_HI + row * (STB * 2) + col * 2;
        char* dl = smg + GA_LO + row * (STB * 2) + col * 2;
        const uint2* hp = reinterpret_cast<const uint2*>(hv);
        const uint2* lp = reinterpret_cast<const uint2*>(lv);
        *reinterpret_cast<uint2*>(dh)     = hp[0];
        *reinterpret_cast<uint2*>(dh + 8) = hp[1];
        *reinterpret_cast<uint2*>(dl)     = lp[0];
        *reinterpret_cast<uint2*>(dl + 8) = lp[1];
    }
    __syncthreads();

    // ---- HMMA mainloop ----
    const int wid = tid >> 5, lane = tid & 31;
    const int wm = (wid >> 1) * 32;       // warp row base (4 warps in M)
    const int wn = (wid & 1) * 64;        // warp col base (2 warps in N)
    const int g = lane >> 2, tg = lane & 3;

    const uint32_t* Ah = reinterpret_cast<const uint32_t*>(smg + GA_HI);
    const uint32_t* Al = reinterpret_cast<const uint32_t*>(smg + GA_LO);
    const uint32_t* Bh = reinterpret_cast<const uint32_t*>(smg + GB_HI);
    const uint32_t* Bl = reinterpret_cast<const uint32_t*>(smg + GB_LO);

    float c[2][8][4];
#pragma unroll
    for (int mt = 0; mt < 2; mt++)
#pragma unroll
        for (int nt = 0; nt < 8; nt++)
#pragma unroll
            for (int e = 0; e < 4; e++) c[mt][nt][e] = 0.f;

#pragma unroll 1
    for (int kc = 0; kc < 8; kc++) {
        const int kw = kc * 8 + tg;
        uint32_t ah[2][4], al[2][4];
#pragma unroll
        for (int mt = 0; mt < 2; mt++) {
            int r0 = wm + mt * 16;
            ah[mt][0] = Ah[(r0 + g)     * STW + kw];
            ah[mt][1] = Ah[(r0 + 8 + g) * STW + kw];
            ah[mt][2] = Ah[(r0 + g)     * STW + kw + 4];
            ah[mt][3] = Ah[(r0 + 8 + g) * STW + kw + 4];
            al[mt][0] = Al[(r0 + g)     * STW + kw];
            al[mt][1] = Al[(r0 + 8 + g) * STW + kw];
            al[mt][2] = Al[(r0 + g)     * STW + kw + 4];
            al[mt][3] = Al[(r0 + 8 + g) * STW + kw + 4];
        }
#pragma unroll
        for (int nt = 0; nt < 8; nt++) {
            int nr = wn + nt * 8 + g;
            uint32_t bh[2], bl[2];
            bh[0] = Bh[nr * STW + kw];
            bh[1] = Bh[nr * STW + kw + 4];
            bl[0] = Bl[nr * STW + kw];
            bl[1] = Bl[nr * STW + kw + 4];
            mma16816(c[0][nt], ah[0], bh);
            mma16816(c[1][nt], ah[1], bh);
            mma16816(c[0][nt], ah[0], bl);
            mma16816(c[1][nt], ah[1], bl);
            mma16816(c[0][nt], al[0], bh);
            mma16816(c[1][nt], al[1], bh);
        }
    }

    // ---- epilogue: + bias, optional q scale, float2 stores ----
    const float scl = (wbase == 0 && by == 0) ? QSCALE : 1.0f;
    const float* bv = bias + by * 128;
#pragma unroll
    for (int mt = 0; mt < 2; mt++) {
#pragma unroll
        for (int nt = 0; nt < 8; nt++) {
            int coll = wn + nt * 8 + 2 * tg;
            float b0 = bv[coll], b1 = bv[coll + 1];
            size_t r0 = mrow0 + wm + mt * 16 + g;
            float2 v0, v1;
            v0.x = (c[mt][nt][0] + b0) * scl;
            v0.y = (c[mt][nt][1] + b1) * scl;
            v1.x = (c[mt][nt][2] + b0) * scl;
            v1.y = (c[mt][nt][3] + b1) * scl;
            *reinterpret_cast<float2*>(out + r0 * ostride + by * 128 + coll) = v0;
            *reinterpret_cast<float2*>(out + (r0 + 8) * ostride + by * 128 + coll) = v1;
        }
    }
}

// ---------------- attention kernel: one (window, head) per CTA ---------------
#define AQ 0
#define AK 3528            // 98*36
#define AV 7056
#define AS 10584           // S[98][100]
#define ATT_FLOATS 20384
#define ATT_BYTES  (ATT_FLOATS * 4)    // 81536

__global__ void __launch_bounds__(256, 2)
attn_kernel(const float* __restrict__ mask) {
    extern __shared__ float sa[];
    const int win = blockIdx.x, h = blockIdx.y;
    const int tid = threadIdx.x, warp = tid >> 5, lane = tid & 31;

    // load q,k,v head slices: 98 rows x 32 cols each
    {
        const float* base = g_qkv + (size_t)win * NTOK * 384 + h * 32;
        for (int idx = tid; idx < NTOK * 24; idx += 256) {
            int row = idx / 24, t = idx % 24;
            int sec = t >> 3, g = t & 7;
            float4 v = *reinterpret_cast<const float4*>(
                base + (size_t)row * 384 + sec * 128 + g * 4);
            *reinterpret_cast<float4*>(&sa[sec * 3528 + row * 36 + g * 4]) = v;
        }
    }
    __syncthreads();

    float* S = sa + AS;
    const float* maskw = mask + (size_t)(win & (NWIN - 1)) * (NTOK * NTOK);
    const float* biash = g_bias + h * (NTOK * NTOK);

    // ---- S = q k^T + bias + mask (two 49-row blocks) ----
#pragma unroll 1
    for (int rb = 0; rb < 2; rb++) {
        const int r0 = rb * 49;
        u64 acc[7][4];
#pragma unroll
        for (int i = 0; i < 7; i++)
#pragma unroll
            for (int j = 0; j < 4; j++) acc[i][j] = 0ull;
#pragma unroll
        for (int d4 = 0; d4 < 8; d4++) {
            ulonglong2 a2[7];
#pragma unroll
            for (int i = 0; i < 6; i++)
                a2[i] = *reinterpret_cast<const ulonglong2*>(
                    &sa[AQ + (r0 + warp + 8 * i) * 36 + d4 * 4]);
            if (warp == 0)
                a2[6] = *reinterpret_cast<const ulonglong2*>(
                    &sa[AQ + (r0 + 48) * 36 + d4 * 4]);
#pragma unroll
            for (int j = 0; j < 4; j++) {
                ulonglong2 b2 = *reinterpret_cast<const ulonglong2*>(
                    &sa[AK + (lane + 32 * j) * 36 + d4 * 4]);
#pragma unroll
                for (int i = 0; i < 6; i++) {
                    fma2(acc[i][j], a2[i].x, b2.x);
                    fma2(acc[i][j], a2[i].y, b2.y);
                }
                if (warp == 0) {
                    fma2(acc[6][j], a2[6].x, b2.x);
                    fma2(acc[6][j], a2[6].y, b2.y);
                }
            }
        }
#pragma unroll
        for (int i = 0; i < 7; i++) {
            if (i < 6 || warp == 0) {
                int gi = r0 + ((i < 6) ? (warp + 8 * i) : 48);
#pragma unroll
                for (int j = 0; j < 4; j++) {
                    int gj = lane + 32 * j;
                    if (gj < NTOK) {
                        float2 pp = unpk2(acc[i][j]);
                        S[gi * 100 + gj] = pp.x + pp.y
                            + biash[gi * NTOK + gj] + maskw[gi * NTOK + gj];
                    }
                }
            }
        }
    }
    __syncthreads();

    // ---- softmax rows warp+8i ----
#pragma unroll 1
    for (int i = 0; i < 13; i++) {
        int r = warp + 8 * i;
        if (r < NTOK) {
            float* Sr = S + r * 100;
            float v0 = Sr[lane], v1 = Sr[lane + 32], v2 = Sr[lane + 64];
            float v3 = (lane < 2) ? Sr[lane + 96] : -3.0e38f;
            float mx = fmaxf(fmaxf(v0, v1), fmaxf(v2, v3));
#pragma unroll
            for (int o = 16; o > 0; o >>= 1)
                mx = fmaxf(mx, __shfl_xor_sync(0xffffffffu, mx, o));
            float e0 = __expf(v0 - mx), e1 = __expf(v1 - mx), e2 = __expf(v2 - mx);
            float e3 = (lane < 2) ? __expf(v3 - mx) : 0.f;
            float s = e0 + e1 + e2 + e3;
#pragma unroll
            for (int o = 16; o > 0; o >>= 1)
                s += __shfl_xor_sync(0xffffffffu, s, o);
            float inv = 1.0f / s;
            Sr[lane]      = e0 * inv;
            Sr[lane + 32] = e1 * inv;
            Sr[lane + 64] = e2 * inv;
            if (lane < 2)      Sr[lane + 96] = e3 * inv;
            else if (lane < 4) Sr[lane + 96] = 0.f;   // zero-pad cols 98,99
        }
    }
    // no block sync needed: PV reads only rows this warp softmaxed

    // ---- O = P V (rows warp+8i, col = lane within head) ----
    {
        u64 po2[13];
#pragma unroll
        for (int i = 0; i < 13; i++) po2[i] = 0ull;
#pragma unroll 5
        for (int j4 = 0; j4 < 25; j4++) {
            float bv0 = sa[AV + (j4 * 4 + 0) * 36 + lane];
            float bv1 = sa[AV + (j4 * 4 + 1) * 36 + lane];
            float bv2 = sa[AV + (j4 * 4 + 2) * 36 + lane];
            float bv3 = sa[AV + (j4 * 4 + 3) * 36 + lane];
            u64 v01 = pack2(bv0, bv1);
            u64 v23 = pack2(bv2, bv3);
#pragma unroll
            for (int i = 0; i < 13; i++) {
                if (i < 12 || warp < 2) {
                    ulonglong2 a2 = *reinterpret_cast<const ulonglong2*>(
                        &S[(warp + 8 * i) * 100 + j4 * 4]);
                    fma2(po2[i], a2.x, v01);
                    fma2(po2[i], a2.y, v23);
                }
            }
        }
#pragma unroll
        for (int i = 0; i < 13; i++) {
            if (i < 12 || warp < 2) {
                int r = warp + 8 * i;
                float2 pp = unpk2(po2[i]);
                g_o[(size_t)(win * NTOK + r) * DIM + h * 32 + lane] = pp.x + pp.y;
            }
        }
    }
}

// ---------------- launch ----------------
extern "C" void kernel_launch(void* const* d_in, const int* in_sizes, int n_in,
                              void* d_out, int out_size) {
    const float* x          = (const float*)d_in[0];
    const float* mask       = (const float*)d_in[1];
    const float* qkv_w      = (const float*)d_in[2];
    const float* qkv_b      = (const float*)d_in[3];
    const float* proj_w     = (const float*)d_in[4];
    const float* proj_b     = (const float*)d_in[5];
    const float* bias_table = (const float*)d_in[6];
    const int*   rel_index  = (const int*)d_in[7];
    float* y = (float*)d_out;
    (void)in_sizes; (void)n_in; (void)out_size;

    cudaFuncSetAttribute(gemm128_kernel,
                         cudaFuncAttributeMaxDynamicSharedMemorySize, GS_TOTAL);
    cudaFuncSetAttribute(attn_kernel,
                         cudaFuncAttributeMaxDynamicSharedMemorySize, ATT_BYTES);

    bias_setup_kernel<<<(NTOK * NTOK + 255) / 256, 256>>>(bias_table, rel_index);
    wimg_setup_kernel<<<256, 256>>>(qkv_w, proj_w);

    // QKV: x @ Wqkv^T + b -> g_qkv [M][384], q scaled
    gemm128_kernel<<<dim3(MTILES, 3), 256, GS_TOTAL>>>(
        x, qkv_b, nullptr, 384, /*wbase=*/0, /*a_scratch=*/0, /*out_scratch=*/1);

    // attention per (window, head)
    attn_kernel<<<dim3(BWIN, HEADS), 256, ATT_BYTES>>>(mask);

    // proj: g_o @ Wp^T + b -> y [M][128]
    gemm128_kernel<<<dim3(MTILES, 1), 256, GS_TOTAL>>>(
        nullptr, proj_b, y, 128, /*wbase=*/3, /*a_scratch=*/1, /*out_scratch=*/0);
}

// round 11
// speedup vs baseline: 1.5837x; 1.1659x over previous
#include <cuda_runtime.h>
#include <cuda_bf16.h>
#include <cstdint>
#include <math.h>

#define DIM   128
#define NTOK  98
#define HEADS 4
#define BWIN  2048
#define NWIN  256
#define MTOT  (BWIN * NTOK)          // 200704 = 1568 * 128
#define MTILES 1568
#define QSCALE 0.17677669529663687f  // 32^-0.5

typedef unsigned long long u64;

// ---------------- f32x2 helpers ----------------
__device__ __forceinline__ u64 pack2(float a, float b) {
    u64 r; asm("mov.b64 %0, {%1, %2};" : "=l"(r) : "f"(a), "f"(b)); return r;
}
__device__ __forceinline__ void fma2(u64& d, u64 a, u64 b) {
    asm("fma.rn.f32x2 %0, %1, %2, %3;" : "=l"(d) : "l"(a), "l"(b), "l"(d));
}
__device__ __forceinline__ float2 unpk2(u64 v) {
    float2 r; asm("mov.b64 {%0, %1}, %2;" : "=f"(r.x), "=f"(r.y) : "l"(v)); return r;
}

// ---------------- HMMA m16n8k16 bf16 ----------------
__device__ __forceinline__ void mma16816(float* c, const uint32_t* a, const uint32_t* b) {
    asm volatile(
        "mma.sync.aligned.m16n8k16.row.col.f32.bf16.bf16.f32 "
        "{%0,%1,%2,%3}, {%4,%5,%6,%7}, {%8,%9}, {%0,%1,%2,%3};"
        : "+f"(c[0]), "+f"(c[1]), "+f"(c[2]), "+f"(c[3])
        : "r"(a[0]), "r"(a[1]), "r"(a[2]), "r"(a[3]), "r"(b[0]), "r"(b[1]));
}

// ---------------- device scratch ----------------
__device__ float g_qkv[(size_t)MTOT * 384];        // q(scaled+biased)|k|v per token
__device__ float g_o[(size_t)MTOT * DIM];          // attention output
__device__ float g_bm[(size_t)HEADS * NWIN * NTOK * 100];  // bias+mask, padded rows
__device__ __nv_bfloat16 g_wimg[4][2][DIM * DIM];  // W[n][k] bf16 hi/lo images

// ---------------- setup kernels ----------------
// combined bias+mask table: g_bm[h][wm][i][j] (j stride 100, cols 98/99 = 0)
__global__ void bm_setup_kernel(const float* __restrict__ bias_table,
                                const int* __restrict__ rel_index,
                                const float* __restrict__ mask) {
    int idx = blockIdx.x * blockDim.x + threadIdx.x;
    const int TOT = HEADS * NWIN * NTOK * 100;
    if (idx < TOT) {
        int j = idx % 100;
        int r = idx / 100;
        int i = r % NTOK;
        int t = r / NTOK;
        int wm = t % NWIN;
        int h = t / NWIN;
        float v = 0.f;
        if (j < NTOK)
            v = bias_table[rel_index[i * NTOK + j] * HEADS + h]
              + mask[(size_t)wm * NTOK * NTOK + i * NTOK + j];
        g_bm[idx] = v;
    }
}

__global__ void wimg_setup_kernel(const float* __restrict__ qkv_w,
                                  const float* __restrict__ proj_w) {
    int idx = blockIdx.x * blockDim.x + threadIdx.x;   // 65536 total
    int t = idx >> 14;
    int n = (idx >> 7) & 127;
    int k = idx & 127;
    float w = (t < 3) ? qkv_w[(size_t)(t * DIM + n) * DIM + k]
                      : proj_w[(size_t)n * DIM + k];
    __nv_bfloat16 hi = __float2bfloat16(w);
    __nv_bfloat16 lo = __float2bfloat16(w - __bfloat162float(hi));
    g_wimg[t][0][n * DIM + k] = hi;
    g_wimg[t][1][n * DIM + k] = lo;
}

// ---------------- GEMM: 128x128 tile, K=128, bf16-split HMMA -----------------
// smem stride: 136 bf16 = 272 B = 68 words (68 % 32 == 4 -> conflict-free frags)
#define STB  136
#define STW  68
#define TILE_B (128 * STB * 2)         // 34816 bytes per array
#define GA_HI  0
#define GA_LO  TILE_B
#define GB_HI  (2 * TILE_B)
#define GB_LO  (3 * TILE_B)
#define GS_TOTAL (4 * TILE_B)          // 139264 B

__global__ void __launch_bounds__(512, 1)
gemm128_kernel(const float* __restrict__ Ax, const float* __restrict__ bias,
               float* __restrict__ yout, int ostride, int wbase,
               int a_scratch, int out_scratch) {
    extern __shared__ char smg[];
    const int tid = threadIdx.x;
    const int by = blockIdx.y;
    const float* __restrict__ Asrc = a_scratch ? g_o : Ax;
    float* __restrict__ out = out_scratch ? g_qkv : yout;
    const size_t mrow0 = (size_t)blockIdx.x * 128;

    // ---- load B tiles (pre-split bf16 images) ----
    {
        const __nv_bfloat16* bh = g_wimg[wbase + by][0];
        const __nv_bfloat16* bl = g_wimg[wbase + by][1];
        for (int i = tid; i < 2048; i += 512) {
            int row = i >> 4, col = (i & 15) * 8;
            uint4 vh = *reinterpret_cast<const uint4*>(bh + row * DIM + col);
            uint4 vl = *reinterpret_cast<const uint4*>(bl + row * DIM + col);
            char* dh = smg + GB_HI + row * (STB * 2) + col * 2;
            char* dl = smg + GB_LO + row * (STB * 2) + col * 2;
            *reinterpret_cast<uint2*>(dh)     = make_uint2(vh.x, vh.y);
            *reinterpret_cast<uint2*>(dh + 8) = make_uint2(vh.z, vh.w);
            *reinterpret_cast<uint2*>(dl)     = make_uint2(vl.x, vl.y);
            *reinterpret_cast<uint2*>(dl + 8) = make_uint2(vl.z, vl.w);
        }
    }
    // ---- load + split A tile ----
    for (int i = tid; i < 2048; i += 512) {
        int row = i >> 4, col = (i & 15) * 8;
        const float* ap = Asrc + (mrow0 + row) * DIM + col;
        float4 f0 = *reinterpret_cast<const float4*>(ap);
        float4 f1 = *reinterpret_cast<const float4*>(ap + 4);
        float fv[8] = {f0.x, f0.y, f0.z, f0.w, f1.x, f1.y, f1.z, f1.w};
        __align__(16) __nv_bfloat16 hv[8], lv[8];
#pragma unroll
        for (int e = 0; e < 8; e++) {
            hv[e] = __float2bfloat16(fv[e]);
            lv[e] = __float2bfloat16(fv[e] - __bfloat162float(hv[e]));
        }
        char* dh = smg + GA_HI + row * (STB * 2) + col * 2;
        char* dl = smg + GA_LO + row * (STB * 2) + col * 2;
        const uint2* hp = reinterpret_cast<const uint2*>(hv);
        const uint2* lp = reinterpret_cast<const uint2*>(lv);
        *reinterpret_cast<uint2*>(dh)     = hp[0];
        *reinterpret_cast<uint2*>(dh + 8) = hp[1];
        *reinterpret_cast<uint2*>(dl)     = lp[0];
        *reinterpret_cast<uint2*>(dl + 8) = lp[1];
    }
    __syncthreads();

    // ---- HMMA mainloop: 16 warps, 4x4 grid, 32x32 warp tiles ----
    const int wid = tid >> 5, lane = tid & 31;
    const int wm = (wid >> 2) * 32;       // warp row base (4 warps in M)
    const int wn = (wid & 3) * 32;        // warp col base (4 warps in N)
    const int g = lane >> 2, tg = lane & 3;

    const uint32_t* Ah = reinterpret_cast<const uint32_t*>(smg + GA_HI);
    const uint32_t* Al = reinterpret_cast<const uint32_t*>(smg + GA_LO);
    const uint32_t* Bh = reinterpret_cast<const uint32_t*>(smg + GB_HI);
    const uint32_t* Bl = reinterpret_cast<const uint32_t*>(smg + GB_LO);

    float c[2][4][4];
#pragma unroll
    for (int mt = 0; mt < 2; mt++)
#pragma unroll
        for (int nt = 0; nt < 4; nt++)
#pragma unroll
            for (int e = 0; e < 4; e++) c[mt][nt][e] = 0.f;

#pragma unroll 1
    for (int kc = 0; kc < 8; kc++) {
        const int kw = kc * 8 + tg;
        uint32_t ah[2][4], al[2][4];
#pragma unroll
        for (int mt = 0; mt < 2; mt++) {
            int r0 = wm + mt * 16;
            ah[mt][0] = Ah[(r0 + g)     * STW + kw];
            ah[mt][1] = Ah[(r0 + 8 + g) * STW + kw];
            ah[mt][2] = Ah[(r0 + g)     * STW + kw + 4];
            ah[mt][3] = Ah[(r0 + 8 + g) * STW + kw + 4];
            al[mt][0] = Al[(r0 + g)     * STW + kw];
            al[mt][1] = Al[(r0 + 8 + g) * STW + kw];
            al[mt][2] = Al[(r0 + g)     * STW + kw + 4];
            al[mt][3] = Al[(r0 + 8 + g) * STW + kw + 4];
        }
#pragma unroll
        for (int nt = 0; nt < 4; nt++) {
            int nr = wn + nt * 8 + g;
            uint32_t bh[2], bl[2];
            bh[0] = Bh[nr * STW + kw];
            bh[1] = Bh[nr * STW + kw + 4];
            bl[0] = Bl[nr * STW + kw];
            bl[1] = Bl[nr * STW + kw + 4];
            mma16816(c[0][nt], ah[0], bh);
            mma16816(c[1][nt], ah[1], bh);
            mma16816(c[0][nt], ah[0], bl);
            mma16816(c[1][nt], ah[1], bl);
            mma16816(c[0][nt], al[0], bh);
            mma16816(c[1][nt], al[1], bh);
        }
    }

    // ---- epilogue: + bias, optional q scale, float2 stores ----
    const float scl = (wbase == 0 && by == 0) ? QSCALE : 1.0f;
    const float* bv = bias + by * 128;
#pragma unroll
    for (int mt = 0; mt < 2; mt++) {
#pragma unroll
        for (int nt = 0; nt < 4; nt++) {
            int coll = wn + nt * 8 + 2 * tg;
            float b0 = bv[coll], b1 = bv[coll + 1];
            size_t r0 = mrow0 + wm + mt * 16 + g;
            float2 v0, v1;
            v0.x = (c[mt][nt][0] + b0) * scl;
            v0.y = (c[mt][nt][1] + b1) * scl;
            v1.x = (c[mt][nt][2] + b0) * scl;
            v1.y = (c[mt][nt][3] + b1) * scl;
            *reinterpret_cast<float2*>(out + r0 * ostride + by * 128 + coll) = v0;
            *reinterpret_cast<float2*>(out + (r0 + 8) * ostride + by * 128 + coll) = v1;
        }
    }
}

// ---------------- attention kernel: one (window, head) per CTA ---------------
#define AQ 0
#define AK 3528            // 98*36
#define AV 7056
#define AS 10584           // S[98][100]
#define ATT_FLOATS 20384
#define ATT_BYTES  (ATT_FLOATS * 4)    // 81536

__global__ void __launch_bounds__(256, 2)
attn_kernel(const float* __restrict__ unused) {
    extern __shared__ float sa[];
    const int win = blockIdx.x, h = blockIdx.y;
    const int tid = threadIdx.x, warp = tid >> 5, lane = tid & 31;

    // prefetch combined bias+mask straight into S region (flat 9800 floats)
    {
        const float4* bmw = reinterpret_cast<const float4*>(
            g_bm + ((size_t)h * NWIN + (win & (NWIN - 1))) * (NTOK * 100));
        float4* Sd = reinterpret_cast<float4*>(sa + AS);
        for (int i = tid; i < 2450; i += 256) Sd[i] = bmw[i];
    }
    // load q,k,v head slices: 98 rows x 32 cols each
    {
        const float* base = g_qkv + (size_t)win * NTOK * 384 + h * 32;
        for (int idx = tid; idx < NTOK * 24; idx += 256) {
            int row = idx / 24, t = idx % 24;
            int sec = t >> 3, g = t & 7;
            float4 v = *reinterpret_cast<const float4*>(
                base + (size_t)row * 384 + sec * 128 + g * 4);
            *reinterpret_cast<float4*>(&sa[sec * 3528 + row * 36 + g * 4]) = v;
        }
    }
    __syncthreads();

    float* S = sa + AS;

    // ---- S = q k^T + (bias+mask pre-loaded in S) (two 49-row blocks) ----
#pragma unroll 1
    for (int rb = 0; rb < 2; rb++) {
        const int r0 = rb * 49;
        u64 acc[7][4];
#pragma unroll
        for (int i = 0; i < 7; i++)
#pragma unroll
            for (int j = 0; j < 4; j++) acc[i][j] = 0ull;
#pragma unroll
        for (int d4 = 0; d4 < 8; d4++) {
            ulonglong2 a2[7];
#pragma unroll
            for (int i = 0; i < 6; i++)
                a2[i] = *reinterpret_cast<const ulonglong2*>(
                    &sa[AQ + (r0 + warp + 8 * i) * 36 + d4 * 4]);
            if (warp == 0)
                a2[6] = *reinterpret_cast<const ulonglong2*>(
                    &sa[AQ + (r0 + 48) * 36 + d4 * 4]);
#pragma unroll
            for (int j = 0; j < 4; j++) {
                ulonglong2 b2 = *reinterpret_cast<const ulonglong2*>(
                    &sa[AK + (lane + 32 * j) * 36 + d4 * 4]);
#pragma unroll
                for (int i = 0; i < 6; i++) {
                    fma2(acc[i][j], a2[i].x, b2.x);
                    fma2(acc[i][j], a2[i].y, b2.y);
                }
                if (warp == 0) {
                    fma2(acc[6][j], a2[6].x, b2.x);
                    fma2(acc[6][j], a2[6].y, b2.y);
                }
            }
        }
#pragma unroll
        for (int i = 0; i < 7; i++) {
            if (i < 6 || warp == 0) {
                int gi = r0 + ((i < 6) ? (warp + 8 * i) : 48);
#pragma unroll
                for (int j = 0; j < 4; j++) {
                    int gj = lane + 32 * j;
                    if (gj < NTOK) {
                        float2 pp = unpk2(acc[i][j]);
                        S[gi * 100 + gj] += pp.x + pp.y;
                    }
                }
            }
        }
    }
    __syncthreads();

    // ---- softmax rows warp+8i ----
#pragma unroll 1
    for (int i = 0; i < 13; i++) {
        int r = warp + 8 * i;
        if (r < NTOK) {
            float* Sr = S + r * 100;
            float v0 = Sr[lane], v1 = Sr[lane + 32], v2 = Sr[lane + 64];
            float v3 = (lane < 2) ? Sr[lane + 96] : -3.0e38f;
            float mx = fmaxf(fmaxf(v0, v1), fmaxf(v2, v3));
#pragma unroll
            for (int o = 16; o > 0; o >>= 1)
                mx = fmaxf(mx, __shfl_xor_sync(0xffffffffu, mx, o));
            float e0 = __expf(v0 - mx), e1 = __expf(v1 - mx), e2 = __expf(v2 - mx);
            float e3 = (lane < 2) ? __expf(v3 - mx) : 0.f;
            float s = e0 + e1 + e2 + e3;
#pragma unroll
            for (int o = 16; o > 0; o >>= 1)
                s += __shfl_xor_sync(0xffffffffu, s, o);
            float inv = 1.0f / s;
            Sr[lane]      = e0 * inv;
            Sr[lane + 32] = e1 * inv;
            Sr[lane + 64] = e2 * inv;
            if (lane < 2)      Sr[lane + 96] = e3 * inv;
            else if (lane < 4) Sr[lane + 96] = 0.f;   // zero-pad cols 98,99
        }
    }
    // no block sync needed: PV reads only rows this warp softmaxed

    // ---- O = P V (rows warp+8i, col = lane within head) ----
    {
        u64 po2[13];
#pragma unroll
        for (int i = 0; i < 13; i++) po2[i] = 0ull;
#pragma unroll 5
        for (int j4 = 0; j4 < 25; j4++) {
            float bv0 = sa[AV + (j4 * 4 + 0) * 36 + lane];
            float bv1 = sa[AV + (j4 * 4 + 1) * 36 + lane];
            float bv2 = sa[AV + (j4 * 4 + 2) * 36 + lane];
            float bv3 = sa[AV + (j4 * 4 + 3) * 36 + lane];
            u64 v01 = pack2(bv0, bv1);
            u64 v23 = pack2(bv2, bv3);
#pragma unroll
            for (int i = 0; i < 13; i++) {
                if (i < 12 || warp < 2) {
                    ulonglong2 a2 = *reinterpret_cast<const ulonglong2*>(
                        &S[(warp + 8 * i) * 100 + j4 * 4]);
                    fma2(po2[i], a2.x, v01);
                    fma2(po2[i], a2.y, v23);
                }
            }
        }
#pragma unroll
        for (int i = 0; i < 13; i++) {
            if (i < 12 || warp < 2) {
                int r = warp + 8 * i;
                float2 pp = unpk2(po2[i]);
                g_o[(size_t)(win * NTOK + r) * DIM + h * 32 + lane] = pp.x + pp.y;
            }
        }
    }
}

// ---------------- launch ----------------
extern "C" void kernel_launch(void* const* d_in, const int* in_sizes, int n_in,
                              void* d_out, int out_size) {
    const float* x          = (const float*)d_in[0];
    const float* mask       = (const float*)d_in[1];
    const float* qkv_w      = (const float*)d_in[2];
    const float* qkv_b      = (const float*)d_in[3];
    const float* proj_w     = (const float*)d_in[4];
    const float* proj_b     = (const float*)d_in[5];
    const float* bias_table = (const float*)d_in[6];
    const int*   rel_index  = (const int*)d_in[7];
    float* y = (float*)d_out;
    (void)in_sizes; (void)n_in; (void)out_size;

    cudaFuncSetAttribute(gemm128_kernel,
                         cudaFuncAttributeMaxDynamicSharedMemorySize, GS_TOTAL);
    cudaFuncSetAttribute(attn_kernel,
                         cudaFuncAttributeMaxDynamicSharedMemorySize, ATT_BYTES);

    const int BM_TOT = HEADS * NWIN * NTOK * 100;
    bm_setup_kernel<<<(BM_TOT + 255) / 256, 256>>>(bias_table, rel_index, mask);
    wimg_setup_kernel<<<256, 256>>>(qkv_w, proj_w);

    // QKV: x @ Wqkv^T + b -> g_qkv [M][384], q scaled
    gemm128_kernel<<<dim3(MTILES, 3), 512, GS_TOTAL>>>(
        x, qkv_b, nullptr, 384, /*wbase=*/0, /*a_scratch=*/0, /*out_scratch=*/1);

    // attention per (window, head)
    attn_kernel<<<dim3(BWIN, HEADS), 256, ATT_BYTES>>>(nullptr);

    // proj: g_o @ Wp^T + b -> y [M][128]
    gemm128_kernel<<<dim3(MTILES, 1), 512, GS_TOTAL>>>(
        nullptr, proj_b, y, 128, /*wbase=*/3, /*a_scratch=*/1, /*out_scratch=*/0);
}

// round 12
// speedup vs baseline: 1.8311x; 1.1562x over previous
#include <cuda_runtime.h>
#include <cuda_bf16.h>
#include <cstdint>
#include <math.h>

#define DIM   128
#define NTOK  98
#define HEADS 4
#define BWIN  2048
#define NWIN  256
#define MTOT  (BWIN * NTOK)          // 200704 = 1568 * 128
#define MTILES 1568
#define QSCALE 0.17677669529663687f  // 32^-0.5

// ---------------- HMMA m16n8k16 bf16 ----------------
__device__ __forceinline__ void mma16816(float* c, const uint32_t* a, const uint32_t* b) {
    asm volatile(
        "mma.sync.aligned.m16n8k16.row.col.f32.bf16.bf16.f32 "
        "{%0,%1,%2,%3}, {%4,%5,%6,%7}, {%8,%9}, {%0,%1,%2,%3};"
        : "+f"(c[0]), "+f"(c[1]), "+f"(c[2]), "+f"(c[3])
        : "r"(a[0]), "r"(a[1]), "r"(a[2]), "r"(a[3]), "r"(b[0]), "r"(b[1]));
}
__device__ __forceinline__ uint32_t prmt(uint32_t a, uint32_t b, uint32_t sel) {
    uint32_t r; asm("prmt.b32 %0, %1, %2, %3;" : "=r"(r) : "r"(a), "r"(b), "r"(sel));
    return r;
}
// pack fp32 -> {hi bf16 (low 16), lo bf16 (high 16)}
__device__ __forceinline__ uint32_t packbf(float x) {
    __nv_bfloat16 h = __float2bfloat16(x);
    float hf = __bfloat162float(h);
    __nv_bfloat16 l = __float2bfloat16(x - hf);
    return (uint32_t)__bfloat16_as_ushort(h) | ((uint32_t)__bfloat16_as_ushort(l) << 16);
}

// ---------------- device scratch ----------------
__device__ uint32_t g_qkvp[(size_t)MTOT * 384];    // packed {hi,lo} bf16 q|k|v
__device__ float g_o[(size_t)MTOT * DIM];          // attention output (fp32)
__device__ float g_bm[(size_t)HEADS * NWIN * NTOK * NTOK];  // bias+mask table
__device__ __nv_bfloat16 g_wimg[4][2][DIM * DIM];  // W[n][k] bf16 hi/lo images

// ---------------- setup kernels ----------------
__global__ void bm_setup_kernel(const float* __restrict__ bias_table,
                                const int* __restrict__ rel_index,
                                const float* __restrict__ mask) {
    int idx = blockIdx.x * blockDim.x + threadIdx.x;
    const int TOT = HEADS * NWIN * NTOK * NTOK;
    if (idx < TOT) {
        int j = idx % NTOK;
        int r = idx / NTOK;
        int i = r % NTOK;
        int t = r / NTOK;
        int wm = t % NWIN;
        int h = t / NWIN;
        g_bm[idx] = bias_table[rel_index[i * NTOK + j] * HEADS + h]
                  + mask[(size_t)wm * NTOK * NTOK + i * NTOK + j];
    }
}

__global__ void wimg_setup_kernel(const float* __restrict__ qkv_w,
                                  const float* __restrict__ proj_w) {
    int idx = blockIdx.x * blockDim.x + threadIdx.x;   // 65536 total
    int t = idx >> 14;
    int n = (idx >> 7) & 127;
    int k = idx & 127;
    float w = (t < 3) ? qkv_w[(size_t)(t * DIM + n) * DIM + k]
                      : proj_w[(size_t)n * DIM + k];
    __nv_bfloat16 hi = __float2bfloat16(w);
    __nv_bfloat16 lo = __float2bfloat16(w - __bfloat162float(hi));
    g_wimg[t][0][n * DIM + k] = hi;
    g_wimg[t][1][n * DIM + k] = lo;
}

// ---------------- GEMM: 128x128 tile, K=128, bf16-split HMMA -----------------
#define STB  136
#define STW  68
#define TILE_B (128 * STB * 2)         // 34816 bytes per array
#define GA_HI  0
#define GA_LO  TILE_B
#define GB_HI  (2 * TILE_B)
#define GB_LO  (3 * TILE_B)
#define GS_TOTAL (4 * TILE_B)          // 139264 B

__global__ void __launch_bounds__(512, 1)
gemm128_kernel(const float* __restrict__ Ax, const float* __restrict__ bias,
               float* __restrict__ yout, int ostride, int wbase,
               int a_scratch, int out_scratch) {
    extern __shared__ char smg[];
    const int tid = threadIdx.x;
    const int by = blockIdx.y;
    const float* __restrict__ Asrc = a_scratch ? g_o : Ax;
    const size_t mrow0 = (size_t)blockIdx.x * 128;

    // ---- load B tiles (pre-split bf16 images) ----
    {
        const __nv_bfloat16* bh = g_wimg[wbase + by][0];
        const __nv_bfloat16* bl = g_wimg[wbase + by][1];
        for (int i = tid; i < 2048; i += 512) {
            int row = i >> 4, col = (i & 15) * 8;
            uint4 vh = *reinterpret_cast<const uint4*>(bh + row * DIM + col);
            uint4 vl = *reinterpret_cast<const uint4*>(bl + row * DIM + col);
            char* dh = smg + GB_HI + row * (STB * 2) + col * 2;
            char* dl = smg + GB_LO + row * (STB * 2) + col * 2;
            *reinterpret_cast<uint2*>(dh)     = make_uint2(vh.x, vh.y);
            *reinterpret_cast<uint2*>(dh + 8) = make_uint2(vh.z, vh.w);
            *reinterpret_cast<uint2*>(dl)     = make_uint2(vl.x, vl.y);
            *reinterpret_cast<uint2*>(dl + 8) = make_uint2(vl.z, vl.w);
        }
    }
    // ---- load + split A tile ----
    for (int i = tid; i < 2048; i += 512) {
        int row = i >> 4, col = (i & 15) * 8;
        const float* ap = Asrc + (mrow0 + row) * DIM + col;
        float4 f0 = *reinterpret_cast<const float4*>(ap);
        float4 f1 = *reinterpret_cast<const float4*>(ap + 4);
        float fv[8] = {f0.x, f0.y, f0.z, f0.w, f1.x, f1.y, f1.z, f1.w};
        __align__(16) __nv_bfloat16 hv[8], lv[8];
#pragma unroll
        for (int e = 0; e < 8; e++) {
            hv[e] = __float2bfloat16(fv[e]);
            lv[e] = __float2bfloat16(fv[e] - __bfloat162float(hv[e]));
        }
        char* dh = smg + GA_HI + row * (STB * 2) + col * 2;
        char* dl = smg + GA_LO + row * (STB * 2) + col * 2;
        const uint2* hp = reinterpret_cast<const uint2*>(hv);
        const uint2* lp = reinterpret_cast<const uint2*>(lv);
        *reinterpret_cast<uint2*>(dh)     = hp[0];
        *reinterpret_cast<uint2*>(dh + 8) = hp[1];
        *reinterpret_cast<uint2*>(dl)     = lp[0];
        *reinterpret_cast<uint2*>(dl + 8) = lp[1];
    }
    __syncthreads();

    // ---- HMMA mainloop: 16 warps, 4x4 grid, 32x32 warp tiles ----
    const int wid = tid >> 5, lane = tid & 31;
    const int wm = (wid >> 2) * 32;
    const int wn = (wid & 3) * 32;
    const int g = lane >> 2, tg = lane & 3;

    const uint32_t* Ah = reinterpret_cast<const uint32_t*>(smg + GA_HI);
    const uint32_t* Al = reinterpret_cast<const uint32_t*>(smg + GA_LO);
    const uint32_t* Bh = reinterpret_cast<const uint32_t*>(smg + GB_HI);
    const uint32_t* Bl = reinterpret_cast<const uint32_t*>(smg + GB_LO);

    float c[2][4][4];
#pragma unroll
    for (int mt = 0; mt < 2; mt++)
#pragma unroll
        for (int nt = 0; nt < 4; nt++)
#pragma unroll
            for (int e = 0; e < 4; e++) c[mt][nt][e] = 0.f;

#pragma unroll 1
    for (int kc = 0; kc < 8; kc++) {
        const int kw = kc * 8 + tg;
        uint32_t ah[2][4], al[2][4];
#pragma unroll
        for (int mt = 0; mt < 2; mt++) {
            int r0 = wm + mt * 16;
            ah[mt][0] = Ah[(r0 + g)     * STW + kw];
            ah[mt][1] = Ah[(r0 + 8 + g) * STW + kw];
            ah[mt][2] = Ah[(r0 + g)     * STW + kw + 4];
            ah[mt][3] = Ah[(r0 + 8 + g) * STW + kw + 4];
            al[mt][0] = Al[(r0 + g)     * STW + kw];
            al[mt][1] = Al[(r0 + 8 + g) * STW + kw];
            al[mt][2] = Al[(r0 + g)     * STW + kw + 4];
            al[mt][3] = Al[(r0 + 8 + g) * STW + kw + 4];
        }
#pragma unroll
        for (int nt = 0; nt < 4; nt++) {
            int nr = wn + nt * 8 + g;
            uint32_t bh[2], bl[2];
            bh[0] = Bh[nr * STW + kw];
            bh[1] = Bh[nr * STW + kw + 4];
            bl[0] = Bl[nr * STW + kw];
            bl[1] = Bl[nr * STW + kw + 4];
            mma16816(c[0][nt], ah[0], bh);
            mma16816(c[1][nt], ah[1], bh);
            mma16816(c[0][nt], ah[0], bl);
            mma16816(c[1][nt], ah[1], bl);
            mma16816(c[0][nt], al[0], bh);
            mma16816(c[1][nt], al[1], bh);
        }
    }

    // ---- epilogue ----
    const float scl = (wbase == 0 && by == 0) ? QSCALE : 1.0f;
    const float* bv = bias + by * 128;
#pragma unroll
    for (int mt = 0; mt < 2; mt++) {
#pragma unroll
        for (int nt = 0; nt < 4; nt++) {
            int coll = wn + nt * 8 + 2 * tg;
            float b0 = bv[coll], b1 = bv[coll + 1];
            size_t r0 = mrow0 + wm + mt * 16 + g;
            float v00 = (c[mt][nt][0] + b0) * scl;
            float v01 = (c[mt][nt][1] + b1) * scl;
            float v10 = (c[mt][nt][2] + b0) * scl;
            float v11 = (c[mt][nt][3] + b1) * scl;
            if (out_scratch) {   // write packed {hi,lo} bf16 to g_qkvp
                uint2 p0 = make_uint2(packbf(v00), packbf(v01));
                uint2 p1 = make_uint2(packbf(v10), packbf(v11));
                *reinterpret_cast<uint2*>(g_qkvp + r0 * ostride + by * 128 + coll) = p0;
                *reinterpret_cast<uint2*>(g_qkvp + (r0 + 8) * ostride + by * 128 + coll) = p1;
            } else {
                *reinterpret_cast<float2*>(yout + r0 * ostride + by * 128 + coll) =
                    make_float2(v00, v01);
                *reinterpret_cast<float2*>(yout + (r0 + 8) * ostride + by * 128 + coll) =
                    make_float2(v10, v11);
            }
        }
    }
}

// ---------------- attention kernel v2: HMMA S and PV -------------------------
// smem (words): q packed [112][40] | k packed [104][40] | vT packed [32][120]
//               | S fp32 / P packed [112][120]
#define SQ   40
#define SVT  120
#define SSP  120
#define OFF_QP 0
#define OFF_KP 4480
#define OFF_VT 8640
#define OFF_SP 12480
#define ATT_WORDS 25920
#define ATT_BYTES (ATT_WORDS * 4)   // 103680

__global__ void __launch_bounds__(256, 2)
attn_kernel() {
    extern __shared__ float sa[];
    uint32_t* su = reinterpret_cast<uint32_t*>(sa);
    const int win = blockIdx.x, h = blockIdx.y;
    const int tid = threadIdx.x, warp = tid >> 5, lane = tid & 31;
    const int g = lane >> 2, tg = lane & 3;

    const uint4* qkvb = reinterpret_cast<const uint4*>(
        g_qkvp + (size_t)win * NTOK * 384 + h * 32);

    // phase 0a: q,k copy (rows < 98)
    for (int i = tid; i < NTOK * 16; i += 256) {
        int row = i >> 4, t = i & 15, sec = t >> 3, f4 = t & 7;
        uint4 v = qkvb[row * 96 + sec * 32 + f4];
        *reinterpret_cast<uint4*>(su + (sec ? OFF_KP : OFF_QP) + row * SQ + f4 * 4) = v;
    }
    // phase 0b: vT scatter (d-major), lanes cover consecutive rows
    for (int i = tid; i < 1024; i += 256) {
        int f4 = i >> 7, row = i & 127;
        if (row < NTOK) {
            uint4 v = qkvb[row * 96 + 64 + f4];
            int d0 = f4 * 4;
            su[OFF_VT + (d0 + 0) * SVT + row] = v.x;
            su[OFF_VT + (d0 + 1) * SVT + row] = v.y;
            su[OFF_VT + (d0 + 2) * SVT + row] = v.z;
            su[OFF_VT + (d0 + 3) * SVT + row] = v.w;
        }
    }
    // phase 0c: zero vT cols 98..111
    for (int i = tid; i < 512; i += 256) {
        int d = i >> 4, j = 96 + (i & 15);
        if (j >= NTOK) su[OFF_VT + d * SVT + j] = 0u;
    }
    __syncthreads();

    const float* bmw = g_bm + ((size_t)h * NWIN + (win & (NWIN - 1))) * (NTOK * NTOK);

    // ---- phase 1: S = q k^T  (warps 0..6, m16 each; N = 13 n8 tiles; K = 2 k16)
    if (warp < 7) {
        const int r0 = warp * 16;
        uint32_t ah[2][4], al[2][4];
#pragma unroll
        for (int kt = 0; kt < 2; kt++) {
            uint2 w00 = *reinterpret_cast<const uint2*>(su + OFF_QP + (r0 + g) * SQ + kt * 16 + 2 * tg);
            uint2 w01 = *reinterpret_cast<const uint2*>(su + OFF_QP + (r0 + 8 + g) * SQ + kt * 16 + 2 * tg);
            uint2 w10 = *reinterpret_cast<const uint2*>(su + OFF_QP + (r0 + g) * SQ + kt * 16 + 8 + 2 * tg);
            uint2 w11 = *reinterpret_cast<const uint2*>(su + OFF_QP + (r0 + 8 + g) * SQ + kt * 16 + 8 + 2 * tg);
            ah[kt][0] = prmt(w00.x, w00.y, 0x5410); al[kt][0] = prmt(w00.x, w00.y, 0x7632);
            ah[kt][1] = prmt(w01.x, w01.y, 0x5410); al[kt][1] = prmt(w01.x, w01.y, 0x7632);
            ah[kt][2] = prmt(w10.x, w10.y, 0x5410); al[kt][2] = prmt(w10.x, w10.y, 0x7632);
            ah[kt][3] = prmt(w11.x, w11.y, 0x5410); al[kt][3] = prmt(w11.x, w11.y, 0x7632);
        }
        float c[13][4];
#pragma unroll
        for (int nt = 0; nt < 13; nt++)
#pragma unroll
            for (int e = 0; e < 4; e++) c[nt][e] = 0.f;

#pragma unroll
        for (int nt = 0; nt < 13; nt++) {
#pragma unroll
            for (int kt = 0; kt < 2; kt++) {
                uint2 u0 = *reinterpret_cast<const uint2*>(su + OFF_KP + (nt * 8 + g) * SQ + kt * 16 + 2 * tg);
                uint2 u1 = *reinterpret_cast<const uint2*>(su + OFF_KP + (nt * 8 + g) * SQ + kt * 16 + 8 + 2 * tg);
                uint32_t bh[2], bl[2];
                bh[0] = prmt(u0.x, u0.y, 0x5410); bl[0] = prmt(u0.x, u0.y, 0x7632);
                bh[1] = prmt(u1.x, u1.y, 0x5410); bl[1] = prmt(u1.x, u1.y, 0x7632);
                mma16816(c[nt], ah[kt], bh);
                mma16816(c[nt], ah[kt], bl);
                mma16816(c[nt], al[kt], bh);
            }
        }
        // epilogue: + (bias+mask) from L2, store fp32 S
        const int row1 = r0 + g, row2 = r0 + 8 + g;
#pragma unroll
        for (int nt = 0; nt < 13; nt++) {
            int col = nt * 8 + 2 * tg;
            if (col < NTOK) {
                if (row1 < NTOK) {
                    float2 bm = *reinterpret_cast<const float2*>(bmw + row1 * NTOK + col);
                    *reinterpret_cast<float2*>(sa + OFF_SP + row1 * SSP + col) =
                        make_float2(c[nt][0] + bm.x, c[nt][1] + bm.y);
                }
                if (row2 < NTOK) {
                    float2 bm = *reinterpret_cast<const float2*>(bmw + row2 * NTOK + col);
                    *reinterpret_cast<float2*>(sa + OFF_SP + row2 * SSP + col) =
                        make_float2(c[nt][2] + bm.x, c[nt][3] + bm.y);
                }
            }
        }
    }
    __syncthreads();

    // ---- phase 2: softmax, write P packed {hi,lo} in place, zero pad cols ----
#pragma unroll 1
    for (int i = 0; i < 13; i++) {
        int r = warp + 8 * i;
        if (r < NTOK) {
            float* Sr = sa + OFF_SP + r * SSP;
            float v0 = Sr[lane], v1 = Sr[lane + 32], v2 = Sr[lane + 64];
            float v3 = (lane < 2) ? Sr[lane + 96] : -3.0e38f;
            float mx = fmaxf(fmaxf(v0, v1), fmaxf(v2, v3));
#pragma unroll
            for (int o = 16; o > 0; o >>= 1)
                mx = fmaxf(mx, __shfl_xor_sync(0xffffffffu, mx, o));
            float e0 = __expf(v0 - mx), e1 = __expf(v1 - mx), e2 = __expf(v2 - mx);
            float e3 = (lane < 2) ? __expf(v3 - mx) : 0.f;
            float s = e0 + e1 + e2 + e3;
#pragma unroll
            for (int o = 16; o > 0; o >>= 1)
                s += __shfl_xor_sync(0xffffffffu, s, o);
            float inv = 1.0f / s;
            uint32_t* Pr = su + OFF_SP + r * SSP;
            Pr[lane]      = packbf(e0 * inv);
            Pr[lane + 32] = packbf(e1 * inv);
            Pr[lane + 64] = packbf(e2 * inv);
            if (lane < 2)       Pr[lane + 96] = packbf(e3 * inv);
            else if (lane < 16) Pr[lane + 96] = 0u;    // zero cols 98..111
        }
    }
    __syncthreads();

    // ---- phase 3: O = P V  (warps 0..6; N = 4 n8 (d), K = 7 k16) ----
    if (warp < 7) {
        const int r0 = warp * 16;
        float c[4][4];
#pragma unroll
        for (int nt = 0; nt < 4; nt++)
#pragma unroll
            for (int e = 0; e < 4; e++) c[nt][e] = 0.f;

#pragma unroll
        for (int kt = 0; kt < 7; kt++) {
            const int kb = kt * 16;
            uint2 w00 = *reinterpret_cast<const uint2*>(su + OFF_SP + (r0 + g) * SSP + kb + 2 * tg);
            uint2 w01 = *reinterpret_cast<const uint2*>(su + OFF_SP + (r0 + 8 + g) * SSP + kb + 2 * tg);
            uint2 w10 = *reinterpret_cast<const uint2*>(su + OFF_SP + (r0 + g) * SSP + kb + 8 + 2 * tg);
            uint2 w11 = *reinterpret_cast<const uint2*>(su + OFF_SP + (r0 + 8 + g) * SSP + kb + 8 + 2 * tg);
            uint32_t ah[4], al[4];
            ah[0] = prmt(w00.x, w00.y, 0x5410); al[0] = prmt(w00.x, w00.y, 0x7632);
            ah[1] = prmt(w01.x, w01.y, 0x5410); al[1] = prmt(w01.x, w01.y, 0x7632);
            ah[2] = prmt(w10.x, w10.y, 0x5410); al[2] = prmt(w10.x, w10.y, 0x7632);
            ah[3] = prmt(w11.x, w11.y, 0x5410); al[3] = prmt(w11.x, w11.y, 0x7632);
#pragma unroll
            for (int nt = 0; nt < 4; nt++) {
                uint2 u0 = *reinterpret_cast<const uint2*>(su + OFF_VT + (nt * 8 + g) * SVT + kb + 2 * tg);
                uint2 u1 = *reinterpret_cast<const uint2*>(su + OFF_VT + (nt * 8 + g) * SVT + kb + 8 + 2 * tg);
                uint32_t bh[2], bl[2];
                bh[0] = prmt(u0.x, u0.y, 0x5410); bl[0] = prmt(u0.x, u0.y, 0x7632);
                bh[1] = prmt(u1.x, u1.y, 0x5410); bl[1] = prmt(u1.x, u1.y, 0x7632);
                mma16816(c[nt], ah, bh);
                mma16816(c[nt], ah, bl);
                mma16816(c[nt], al, bh);
            }
        }
        const int row1 = r0 + g, row2 = r0 + 8 + g;
        float* ob = g_o + (size_t)win * NTOK * DIM + h * 32;
#pragma unroll
        for (int nt = 0; nt < 4; nt++) {
            int col = nt * 8 + 2 * tg;
            if (row1 < NTOK)
                *reinterpret_cast<float2*>(ob + row1 * DIM + col) = make_float2(c[nt][0], c[nt][1]);
            if (row2 < NTOK)
                *reinterpret_cast<float2*>(ob + row2 * DIM + col) = make_float2(c[nt][2], c[nt][3]);
        }
    }
}

// ---------------- launch ----------------
extern "C" void kernel_launch(void* const* d_in, const int* in_sizes, int n_in,
                              void* d_out, int out_size) {
    const float* x          = (const float*)d_in[0];
    const float* mask       = (const float*)d_in[1];
    const float* qkv_w      = (const float*)d_in[2];
    const float* qkv_b      = (const float*)d_in[3];
    const float* proj_w     = (const float*)d_in[4];
    const float* proj_b     = (const float*)d_in[5];
    const float* bias_table = (const float*)d_in[6];
    const int*   rel_index  = (const int*)d_in[7];
    float* y = (float*)d_out;
    (void)in_sizes; (void)n_in; (void)out_size;

    cudaFuncSetAttribute(gemm128_kernel,
                         cudaFuncAttributeMaxDynamicSharedMemorySize, GS_TOTAL);
    cudaFuncSetAttribute(attn_kernel,
                         cudaFuncAttributeMaxDynamicSharedMemorySize, ATT_BYTES);

    const int BM_TOT = HEADS * NWIN * NTOK * NTOK;
    bm_setup_kernel<<<(BM_TOT + 255) / 256, 256>>>(bias_table, rel_index, mask);
    wimg_setup_kernel<<<256, 256>>>(qkv_w, proj_w);

    // QKV: x @ Wqkv^T + b -> g_qkvp packed bf16 hi/lo [M][384], q scaled
    gemm128_kernel<<<dim3(MTILES, 3), 512, GS_TOTAL>>>(
        x, qkv_b, nullptr, 384, /*wbase=*/0, /*a_scratch=*/0, /*out_scratch=*/1);

    // attention per (window, head)
    attn_kernel<<<dim3(BWIN, HEADS), 256, ATT_BYTES>>>();

    // proj: g_o @ Wp^T + b -> y [M][128]
    gemm128_kernel<<<dim3(MTILES, 1), 512, GS_TOTAL>>>(
        nullptr, proj_b, y, 128, /*wbase=*/3, /*a_scratch=*/1, /*out_scratch=*/0);
}

// round 13
// speedup vs baseline: 2.2955x; 1.2536x over previous
#include <cuda_runtime.h>
#include <cuda_bf16.h>
#include <cstdint>
#include <math.h>

#define DIM   128
#define NTOK  98
#define HEADS 4
#define BWIN  2048
#define NWIN  256
#define MTOT  (BWIN * NTOK)          // 200704 = 1568 * 128
#define MTILES 1568
#define QSCALE 0.17677669529663687f  // 32^-0.5

// ---------------- HMMA m16n8k16 bf16 ----------------
__device__ __forceinline__ void mma16816(float* c, const uint32_t* a, const uint32_t* b) {
    asm volatile(
        "mma.sync.aligned.m16n8k16.row.col.f32.bf16.bf16.f32 "
        "{%0,%1,%2,%3}, {%4,%5,%6,%7}, {%8,%9}, {%0,%1,%2,%3};"
        : "+f"(c[0]), "+f"(c[1]), "+f"(c[2]), "+f"(c[3])
        : "r"(a[0]), "r"(a[1]), "r"(a[2]), "r"(a[3]), "r"(b[0]), "r"(b[1]));
}
__device__ __forceinline__ uint32_t prmt(uint32_t a, uint32_t b, uint32_t sel) {
    uint32_t r; asm("prmt.b32 %0, %1, %2, %3;" : "=r"(r) : "r"(a), "r"(b), "r"(sel));
    return r;
}
// pack fp32 -> {hi bf16 (low 16), lo bf16 (high 16)}
__device__ __forceinline__ uint32_t packbf(float x) {
    __nv_bfloat16 h = __float2bfloat16(x);
    float hf = __bfloat162float(h);
    __nv_bfloat16 l = __float2bfloat16(x - hf);
    return (uint32_t)__bfloat16_as_ushort(h) | ((uint32_t)__bfloat16_as_ushort(l) << 16);
}
// pack pair (p0,p1) -> hi frag {bf16(p0), bf16(p1)} and lo frag of residuals
__device__ __forceinline__ void packpair(float p0, float p1, uint32_t& hi, uint32_t& lo) {
    __nv_bfloat16 h0 = __float2bfloat16(p0), h1 = __float2bfloat16(p1);
    float l0 = p0 - __bfloat162float(h0), l1 = p1 - __bfloat162float(h1);
    __nv_bfloat16 e0 = __float2bfloat16(l0), e1 = __float2bfloat16(l1);
    hi = (uint32_t)__bfloat16_as_ushort(h0) | ((uint32_t)__bfloat16_as_ushort(h1) << 16);
    lo = (uint32_t)__bfloat16_as_ushort(e0) | ((uint32_t)__bfloat16_as_ushort(e1) << 16);
}

// ---------------- device scratch ----------------
__device__ uint32_t g_qkvp[(size_t)MTOT * 384];    // packed {hi,lo} bf16 q|k|v
__device__ float g_o[(size_t)MTOT * DIM];          // attention output (fp32)
__device__ float g_bm[(size_t)HEADS * NWIN * NTOK * NTOK];  // bias+mask table
__device__ __nv_bfloat16 g_wimg[4][2][DIM * DIM];  // W[n][k] bf16 hi/lo images

// ---------------- setup kernels ----------------
__global__ void bm_setup_kernel(const float* __restrict__ bias_table,
                                const int* __restrict__ rel_index,
                                const float* __restrict__ mask) {
    int idx = blockIdx.x * blockDim.x + threadIdx.x;
    const int TOT = HEADS * NWIN * NTOK * NTOK;
    if (idx < TOT) {
        int j = idx % NTOK;
        int r = idx / NTOK;
        int i = r % NTOK;
        int t = r / NTOK;
        int wm = t % NWIN;
        int h = t / NWIN;
        g_bm[idx] = bias_table[rel_index[i * NTOK + j] * HEADS + h]
                  + mask[(size_t)wm * NTOK * NTOK + i * NTOK + j];
    }
}

__global__ void wimg_setup_kernel(const float* __restrict__ qkv_w,
                                  const float* __restrict__ proj_w) {
    int idx = blockIdx.x * blockDim.x + threadIdx.x;   // 65536 total
    int t = idx >> 14;
    int n = (idx >> 7) & 127;
    int k = idx & 127;
    float w = (t < 3) ? qkv_w[(size_t)(t * DIM + n) * DIM + k]
                      : proj_w[(size_t)n * DIM + k];
    __nv_bfloat16 hi = __float2bfloat16(w);
    __nv_bfloat16 lo = __float2bfloat16(w - __bfloat162float(hi));
    g_wimg[t][0][n * DIM + k] = hi;
    g_wimg[t][1][n * DIM + k] = lo;
}

// ---------------- GEMM: 128x128 tile, K=128, bf16-split HMMA -----------------
#define STB  136
#define STW  68
#define TILE_B (128 * STB * 2)         // 34816 bytes per array
#define GA_HI  0
#define GA_LO  TILE_B
#define GB_HI  (2 * TILE_B)
#define GB_LO  (3 * TILE_B)
#define GS_TOTAL (4 * TILE_B)          // 139264 B

__global__ void __launch_bounds__(512, 1)
gemm128_kernel(const float* __restrict__ Ax, const float* __restrict__ bias,
               float* __restrict__ yout, int ostride, int wbase,
               int a_scratch, int out_scratch) {
    extern __shared__ char smg[];
    const int tid = threadIdx.x;
    const int by = blockIdx.y;
    const float* __restrict__ Asrc = a_scratch ? g_o : Ax;
    const size_t mrow0 = (size_t)blockIdx.x * 128;

    // ---- load B tiles (pre-split bf16 images) ----
    {
        const __nv_bfloat16* bh = g_wimg[wbase + by][0];
        const __nv_bfloat16* bl = g_wimg[wbase + by][1];
        for (int i = tid; i < 2048; i += 512) {
            int row = i >> 4, col = (i & 15) * 8;
            uint4 vh = *reinterpret_cast<const uint4*>(bh + row * DIM + col);
            uint4 vl = *reinterpret_cast<const uint4*>(bl + row * DIM + col);
            char* dh = smg + GB_HI + row * (STB * 2) + col * 2;
            char* dl = smg + GB_LO + row * (STB * 2) + col * 2;
            *reinterpret_cast<uint2*>(dh)     = make_uint2(vh.x, vh.y);
            *reinterpret_cast<uint2*>(dh + 8) = make_uint2(vh.z, vh.w);
            *reinterpret_cast<uint2*>(dl)     = make_uint2(vl.x, vl.y);
            *reinterpret_cast<uint2*>(dl + 8) = make_uint2(vl.z, vl.w);
        }
    }
    // ---- load + split A tile ----
    for (int i = tid; i < 2048; i += 512) {
        int row = i >> 4, col = (i & 15) * 8;
        const float* ap = Asrc + (mrow0 + row) * DIM + col;
        float4 f0 = *reinterpret_cast<const float4*>(ap);
        float4 f1 = *reinterpret_cast<const float4*>(ap + 4);
        float fv[8] = {f0.x, f0.y, f0.z, f0.w, f1.x, f1.y, f1.z, f1.w};
        __align__(16) __nv_bfloat16 hv[8], lv[8];
#pragma unroll
        for (int e = 0; e < 8; e++) {
            hv[e] = __float2bfloat16(fv[e]);
            lv[e] = __float2bfloat16(fv[e] - __bfloat162float(hv[e]));
        }
        char* dh = smg + GA_HI + row * (STB * 2) + col * 2;
        char* dl = smg + GA_LO + row * (STB * 2) + col * 2;
        const uint2* hp = reinterpret_cast<const uint2*>(hv);
        const uint2* lp = reinterpret_cast<const uint2*>(lv);
        *reinterpret_cast<uint2*>(dh)     = hp[0];
        *reinterpret_cast<uint2*>(dh + 8) = hp[1];
        *reinterpret_cast<uint2*>(dl)     = lp[0];
        *reinterpret_cast<uint2*>(dl + 8) = lp[1];
    }
    __syncthreads();

    // ---- HMMA mainloop: 16 warps, 4x4 grid, 32x32 warp tiles ----
    const int wid = tid >> 5, lane = tid & 31;
    const int wm = (wid >> 2) * 32;
    const int wn = (wid & 3) * 32;
    const int g = lane >> 2, tg = lane & 3;

    const uint32_t* Ah = reinterpret_cast<const uint32_t*>(smg + GA_HI);
    const uint32_t* Al = reinterpret_cast<const uint32_t*>(smg + GA_LO);
    const uint32_t* Bh = reinterpret_cast<const uint32_t*>(smg + GB_HI);
    const uint32_t* Bl = reinterpret_cast<const uint32_t*>(smg + GB_LO);

    float c[2][4][4];
#pragma unroll
    for (int mt = 0; mt < 2; mt++)
#pragma unroll
        for (int nt = 0; nt < 4; nt++)
#pragma unroll
            for (int e = 0; e < 4; e++) c[mt][nt][e] = 0.f;

#pragma unroll 1
    for (int kc = 0; kc < 8; kc++) {
        const int kw = kc * 8 + tg;
        uint32_t ah[2][4], al[2][4];
#pragma unroll
        for (int mt = 0; mt < 2; mt++) {
            int r0 = wm + mt * 16;
            ah[mt][0] = Ah[(r0 + g)     * STW + kw];
            ah[mt][1] = Ah[(r0 + 8 + g) * STW + kw];
            ah[mt][2] = Ah[(r0 + g)     * STW + kw + 4];
            ah[mt][3] = Ah[(r0 + 8 + g) * STW + kw + 4];
            al[mt][0] = Al[(r0 + g)     * STW + kw];
            al[mt][1] = Al[(r0 + 8 + g) * STW + kw];
            al[mt][2] = Al[(r0 + g)     * STW + kw + 4];
            al[mt][3] = Al[(r0 + 8 + g) * STW + kw + 4];
        }
#pragma unroll
        for (int nt = 0; nt < 4; nt++) {
            int nr = wn + nt * 8 + g;
            uint32_t bh[2], bl[2];
            bh[0] = Bh[nr * STW + kw];
            bh[1] = Bh[nr * STW + kw + 4];
            bl[0] = Bl[nr * STW + kw];
            bl[1] = Bl[nr * STW + kw + 4];
            mma16816(c[0][nt], ah[0], bh);
            mma16816(c[1][nt], ah[1], bh);
            mma16816(c[0][nt], ah[0], bl);
            mma16816(c[1][nt], ah[1], bl);
            mma16816(c[0][nt], al[0], bh);
            mma16816(c[1][nt], al[1], bh);
        }
    }

    // ---- epilogue ----
    const float scl = (wbase == 0 && by == 0) ? QSCALE : 1.0f;
    const float* bv = bias + by * 128;
#pragma unroll
    for (int mt = 0; mt < 2; mt++) {
#pragma unroll
        for (int nt = 0; nt < 4; nt++) {
            int coll = wn + nt * 8 + 2 * tg;
            float b0 = bv[coll], b1 = bv[coll + 1];
            size_t r0 = mrow0 + wm + mt * 16 + g;
            float v00 = (c[mt][nt][0] + b0) * scl;
            float v01 = (c[mt][nt][1] + b1) * scl;
            float v10 = (c[mt][nt][2] + b0) * scl;
            float v11 = (c[mt][nt][3] + b1) * scl;
            if (out_scratch) {   // write packed {hi,lo} bf16 to g_qkvp
                uint2 p0 = make_uint2(packbf(v00), packbf(v01));
                uint2 p1 = make_uint2(packbf(v10), packbf(v11));
                *reinterpret_cast<uint2*>(g_qkvp + r0 * ostride + by * 128 + coll) = p0;
                *reinterpret_cast<uint2*>(g_qkvp + (r0 + 8) * ostride + by * 128 + coll) = p1;
            } else {
                *reinterpret_cast<float2*>(yout + r0 * ostride + by * 128 + coll) =
                    make_float2(v00, v01);
                *reinterpret_cast<float2*>(yout + (r0 + 8) * ostride + by * 128 + coll) =
                    make_float2(v10, v11);
            }
        }
    }
}

// ---------------- attention kernel v3: register-resident softmax + P ---------
// smem (u32 words): k packed [104][40] | vT packed [32][120]
#define KP    0
#define KS    40
#define VT    4160
#define VS    120
#define ATT_WORDS (4160 + 3840)
#define ATT_BYTES (ATT_WORDS * 4)   // 32000

__global__ void __launch_bounds__(224, 2)
attn_kernel() {
    extern __shared__ uint32_t su[];
    const int win = blockIdx.x, h = blockIdx.y;
    const int tid = threadIdx.x, warp = tid >> 5, lane = tid & 31;
    const int g = lane >> 2, tg = lane & 3;

    const uint32_t* qb = g_qkvp + (size_t)win * NTOK * 384 + h * 32;
    const uint4* qkvb = reinterpret_cast<const uint4*>(qb);

    // load k into smem (rows 98..103 zeroed)
    for (int i = tid; i < 104 * 8; i += 224) {
        int row = i >> 3, f4 = i & 7;
        uint4 v = (row < NTOK) ? qkvb[row * 96 + 32 + f4]
                               : make_uint4(0u, 0u, 0u, 0u);
        *reinterpret_cast<uint4*>(su + KP + row * KS + f4 * 4) = v;
    }
    // load vT (d-major); cols 98..111 zeroed
    for (int i = tid; i < 1024; i += 224) {
        int f4 = i >> 7, row = i & 127;
        int d0 = f4 * 4;
        if (row < NTOK) {
            uint4 v = qkvb[row * 96 + 64 + f4];
            su[VT + (d0 + 0) * VS + row] = v.x;
            su[VT + (d0 + 1) * VS + row] = v.y;
            su[VT + (d0 + 2) * VS + row] = v.z;
            su[VT + (d0 + 3) * VS + row] = v.w;
        } else if (row < 112) {
            su[VT + (d0 + 0) * VS + row] = 0u;
            su[VT + (d0 + 1) * VS + row] = 0u;
            su[VT + (d0 + 2) * VS + row] = 0u;
            su[VT + (d0 + 3) * VS + row] = 0u;
        }
    }
    __syncthreads();

    const int r0 = warp * 16;
    const int row1 = r0 + g, row2 = r0 + 8 + g;
    const int qr1 = (row1 < NTOK) ? row1 : (NTOK - 1);
    const int qr2 = (row2 < NTOK) ? row2 : (NTOK - 1);

    // ---- q A-fragments direct from gmem (packed {hi,lo}) ----
    uint32_t ah[2][4], al[2][4];
#pragma unroll
    for (int kt = 0; kt < 2; kt++) {
        uint2 w00 = *reinterpret_cast<const uint2*>(qb + qr1 * 384 + kt * 16 + 2 * tg);
        uint2 w01 = *reinterpret_cast<const uint2*>(qb + qr2 * 384 + kt * 16 + 2 * tg);
        uint2 w10 = *reinterpret_cast<const uint2*>(qb + qr1 * 384 + kt * 16 + 8 + 2 * tg);
        uint2 w11 = *reinterpret_cast<const uint2*>(qb + qr2 * 384 + kt * 16 + 8 + 2 * tg);
        ah[kt][0] = prmt(w00.x, w00.y, 0x5410); al[kt][0] = prmt(w00.x, w00.y, 0x7632);
        ah[kt][1] = prmt(w01.x, w01.y, 0x5410); al[kt][1] = prmt(w01.x, w01.y, 0x7632);
        ah[kt][2] = prmt(w10.x, w10.y, 0x5410); al[kt][2] = prmt(w10.x, w10.y, 0x7632);
        ah[kt][3] = prmt(w11.x, w11.y, 0x5410); al[kt][3] = prmt(w11.x, w11.y, 0x7632);
    }

    // ---- S = q k^T: c[14 n-tiles][4]; tile 13 (cols 104..111) preset -inf ----
    float c[14][4];
#pragma unroll
    for (int nt = 0; nt < 13; nt++)
#pragma unroll
        for (int e = 0; e < 4; e++) c[nt][e] = 0.f;
#pragma unroll
    for (int e = 0; e < 4; e++) c[13][e] = -1.0e30f;

#pragma unroll
    for (int nt = 0; nt < 13; nt++) {
#pragma unroll
        for (int kt = 0; kt < 2; kt++) {
            uint2 u0 = *reinterpret_cast<const uint2*>(su + KP + (nt * 8 + g) * KS + kt * 16 + 2 * tg);
            uint2 u1 = *reinterpret_cast<const uint2*>(su + KP + (nt * 8 + g) * KS + kt * 16 + 8 + 2 * tg);
            uint32_t bh[2], bl[2];
            bh[0] = prmt(u0.x, u0.y, 0x5410); bl[0] = prmt(u0.x, u0.y, 0x7632);
            bh[1] = prmt(u1.x, u1.y, 0x5410); bl[1] = prmt(u1.x, u1.y, 0x7632);
            mma16816(c[nt], ah[kt], bh);
            mma16816(c[nt], ah[kt], bl);
            mma16816(c[nt], al[kt], bh);
        }
    }

    // ---- + bias+mask (L2), invalidate out-of-range rows/cols ----
    const float* bmw = g_bm + ((size_t)h * NWIN + (win & (NWIN - 1))) * (NTOK * NTOK);
#pragma unroll
    for (int nt = 0; nt < 13; nt++) {
        int col = nt * 8 + 2 * tg;
        if (col < NTOK) {
            if (row1 < NTOK) {
                float2 bm = *reinterpret_cast<const float2*>(bmw + row1 * NTOK + col);
                c[nt][0] += bm.x; c[nt][1] += bm.y;
            } else { c[nt][0] = -1.0e30f; c[nt][1] = -1.0e30f; }
            if (row2 < NTOK) {
                float2 bm = *reinterpret_cast<const float2*>(bmw + row2 * NTOK + col);
                c[nt][2] += bm.x; c[nt][3] += bm.y;
            } else { c[nt][2] = -1.0e30f; c[nt][3] = -1.0e30f; }
        } else {
            c[nt][0] = c[nt][1] = c[nt][2] = c[nt][3] = -1.0e30f;
        }
    }

    // ---- softmax in registers (rows spread over the 4-lane quad) ----
    float m1 = -3.0e38f, m2 = -3.0e38f;
#pragma unroll
    for (int nt = 0; nt < 14; nt++) {
        m1 = fmaxf(m1, fmaxf(c[nt][0], c[nt][1]));
        m2 = fmaxf(m2, fmaxf(c[nt][2], c[nt][3]));
    }
#pragma unroll
    for (int o = 1; o < 4; o <<= 1) {
        m1 = fmaxf(m1, __shfl_xor_sync(0xffffffffu, m1, o));
        m2 = fmaxf(m2, __shfl_xor_sync(0xffffffffu, m2, o));
    }
    float s1 = 0.f, s2 = 0.f;
#pragma unroll
    for (int nt = 0; nt < 14; nt++) {
        c[nt][0] = __expf(c[nt][0] - m1); c[nt][1] = __expf(c[nt][1] - m1);
        c[nt][2] = __expf(c[nt][2] - m2); c[nt][3] = __expf(c[nt][3] - m2);
        s1 += c[nt][0] + c[nt][1];
        s2 += c[nt][2] + c[nt][3];
    }
#pragma unroll
    for (int o = 1; o < 4; o <<= 1) {
        s1 += __shfl_xor_sync(0xffffffffu, s1, o);
        s2 += __shfl_xor_sync(0xffffffffu, s2, o);
    }
    const float i1 = 1.0f / s1, i2 = 1.0f / s2;
#pragma unroll
    for (int nt = 0; nt < 14; nt++) {
        c[nt][0] *= i1; c[nt][1] *= i1;
        c[nt][2] *= i2; c[nt][3] *= i2;
    }

    // ---- PV: c IS the A-fragment layout; pack and multiply ----
    float cpv[4][4];
#pragma unroll
    for (int nt = 0; nt < 4; nt++)
#pragma unroll
        for (int e = 0; e < 4; e++) cpv[nt][e] = 0.f;

#pragma unroll
    for (int kt = 0; kt < 7; kt++) {
        uint32_t pah[4], pal[4];
        packpair(c[2 * kt][0],     c[2 * kt][1],     pah[0], pal[0]);
        packpair(c[2 * kt][2],     c[2 * kt][3],     pah[1], pal[1]);
        packpair(c[2 * kt + 1][0], c[2 * kt + 1][1], pah[2], pal[2]);
        packpair(c[2 * kt + 1][2], c[2 * kt + 1][3], pah[3], pal[3]);
        const int kb = kt * 16;
#pragma unroll
        for (int nt = 0; nt < 4; nt++) {
            uint2 u0 = *reinterpret_cast<const uint2*>(su + VT + (nt * 8 + g) * VS + kb + 2 * tg);
            uint2 u1 = *reinterpret_cast<const uint2*>(su + VT + (nt * 8 + g) * VS + kb + 8 + 2 * tg);
            uint32_t bh[2], bl[2];
            bh[0] = prmt(u0.x, u0.y, 0x5410); bl[0] = prmt(u0.x, u0.y, 0x7632);
            bh[1] = prmt(u1.x, u1.y, 0x5410); bl[1] = prmt(u1.x, u1.y, 0x7632);
            mma16816(cpv[nt], pah, bh);
            mma16816(cpv[nt], pah, bl);
            mma16816(cpv[nt], pal, bh);
        }
    }

    // ---- store O ----
    float* ob = g_o + (size_t)win * NTOK * DIM + h * 32;
#pragma unroll
    for (int nt = 0; nt < 4; nt++) {
        int col = nt * 8 + 2 * tg;
        if (row1 < NTOK)
            *reinterpret_cast<float2*>(ob + row1 * DIM + col) = make_float2(cpv[nt][0], cpv[nt][1]);
        if (row2 < NTOK)
            *reinterpret_cast<float2*>(ob + row2 * DIM + col) = make_float2(cpv[nt][2], cpv[nt][3]);
    }
}

// ---------------- launch ----------------
extern "C" void kernel_launch(void* const* d_in, const int* in_sizes, int n_in,
                              void* d_out, int out_size) {
    const float* x          = (const float*)d_in[0];
    const float* mask       = (const float*)d_in[1];
    const float* qkv_w      = (const float*)d_in[2];
    const float* qkv_b      = (const float*)d_in[3];
    const float* proj_w     = (const float*)d_in[4];
    const float* proj_b     = (const float*)d_in[5];
    const float* bias_table = (const float*)d_in[6];
    const int*   rel_index  = (const int*)d_in[7];
    float* y = (float*)d_out;
    (void)in_sizes; (void)n_in; (void)out_size;

    cudaFuncSetAttribute(gemm128_kernel,
                         cudaFuncAttributeMaxDynamicSharedMemorySize, GS_TOTAL);
    cudaFuncSetAttribute(attn_kernel,
                         cudaFuncAttributeMaxDynamicSharedMemorySize, ATT_BYTES);

    const int BM_TOT = HEADS * NWIN * NTOK * NTOK;
    bm_setup_kernel<<<(BM_TOT + 255) / 256, 256>>>(bias_table, rel_index, mask);
    wimg_setup_kernel<<<256, 256>>>(qkv_w, proj_w);

    // QKV: x @ Wqkv^T + b -> g_qkvp packed bf16 hi/lo [M][384], q scaled
    gemm128_kernel<<<dim3(MTILES, 3), 512, GS_TOTAL>>>(
        x, qkv_b, nullptr, 384, /*wbase=*/0, /*a_scratch=*/0, /*out_scratch=*/1);

    // attention per (window, head)
    attn_kernel<<<dim3(BWIN, HEADS), 224, ATT_BYTES>>>();

    // proj: g_o @ Wp^T + b -> y [M][128]
    gemm128_kernel<<<dim3(MTILES, 1), 512, GS_TOTAL>>>(
        nullptr, proj_b, y, 128, /*wbase=*/3, /*a_scratch=*/1, /*out_scratch=*/0);
}